// round 1
// baseline (speedup 1.0000x reference)
#include <cuda_runtime.h>
#include <cstdint>

#define NN 12288
#define EE 196608
#define DD 64

// scratch (device globals — no allocation allowed)
__device__ float g_R[NN * DD];    // relu(x @ W_high^T)
__device__ float g_XW[NN * DD];   // x @ W_conv^T
__device__ float g_HL[NN * DD];   // scatter accumulation (edges only)
__device__ float g_dinv[NN];
__device__ int   g_deg[NN];

// ---------------------------------------------------------------------------
// init: zero HL and out, deg = 1 (self loop)
// ---------------------------------------------------------------------------
__global__ void k_init(float* __restrict__ out) {
    int i = blockIdx.x * 256 + threadIdx.x;   // grid sized to NN*DD exactly
    g_HL[i] = 0.0f;
    out[i]  = 0.0f;
    if (i < NN) g_deg[i] = 1;
}

// ---------------------------------------------------------------------------
// degree over edge targets
// ---------------------------------------------------------------------------
__global__ void k_deg(const int* __restrict__ ei) {
    int e = blockIdx.x * 256 + threadIdx.x;
    if (e < EE) atomicAdd(&g_deg[ei[EE + e]], 1);
}

__global__ void k_dinv() {
    int i = blockIdx.x * 256 + threadIdx.x;
    if (i < NN) g_dinv[i] = rsqrtf((float)g_deg[i]);
}

// ---------------------------------------------------------------------------
// R = relu(x @ Wh^T), XW = x @ Wc^T.  Block = 256 thr handles 64 nodes.
// SMEM exactly 48KB (3 x 64x64 f32). Reads: sXt contiguous, W uniform bcast.
// ---------------------------------------------------------------------------
__global__ void __launch_bounds__(256) k_xw(const float* __restrict__ x,
                                            const float* __restrict__ Wh,
                                            const float* __restrict__ Wc) {
    __shared__ float sXt[64][64];
    __shared__ float sWhT[64][64];
    __shared__ float sWcT[64][64];
    int tid = threadIdx.x;
    int nb  = blockIdx.x * 64;

#pragma unroll
    for (int it = 0; it < 4; ++it) {
        int idx = tid + it * 256;          // 0..1023 float4 slots
        int r   = idx >> 4;
        int c4  = idx & 15;
        float4 vx = *(const float4*)&x[(size_t)(nb + r) * 64 + c4 * 4];
        sXt[c4 * 4 + 0][r] = vx.x; sXt[c4 * 4 + 1][r] = vx.y;
        sXt[c4 * 4 + 2][r] = vx.z; sXt[c4 * 4 + 3][r] = vx.w;
        float4 vh = *(const float4*)&Wh[r * 64 + c4 * 4];
        sWhT[c4 * 4 + 0][r] = vh.x; sWhT[c4 * 4 + 1][r] = vh.y;
        sWhT[c4 * 4 + 2][r] = vh.z; sWhT[c4 * 4 + 3][r] = vh.w;
        float4 vc = *(const float4*)&Wc[r * 64 + c4 * 4];
        sWcT[c4 * 4 + 0][r] = vc.x; sWcT[c4 * 4 + 1][r] = vc.y;
        sWcT[c4 * 4 + 2][r] = vc.z; sWcT[c4 * 4 + 3][r] = vc.w;
    }
    __syncthreads();

    int n  = tid & 63;
    int cg = tid >> 6;                     // 0..3 -> 16-col group
    float aR[16], aC[16];
#pragma unroll
    for (int c = 0; c < 16; ++c) { aR[c] = 0.f; aC[c] = 0.f; }

#pragma unroll 4
    for (int k = 0; k < 64; ++k) {
        float xv = sXt[k][n];
#pragma unroll
        for (int c = 0; c < 16; ++c) {
            aR[c] += xv * sWhT[k][cg * 16 + c];
            aC[c] += xv * sWcT[k][cg * 16 + c];
        }
    }
    size_t base = (size_t)(nb + n) * 64 + cg * 16;
#pragma unroll
    for (int c = 0; c < 16; ++c) {
        g_R[base + c]  = fmaxf(aR[c], 0.0f);
        g_XW[base + c] = aC[c];
    }
}

// ---------------------------------------------------------------------------
// edge scatter: HL[col] += dinv[row]*dinv[col] * XW[row]
// one thread per (edge, float4-chunk): E*16 threads
// ---------------------------------------------------------------------------
__global__ void __launch_bounds__(256) k_scatter(const int* __restrict__ ei) {
    int t = blockIdx.x * 256 + threadIdx.x;   // grid sized to EE*16
    int e = t >> 4;
    int q = t & 15;
    int r = ei[e];
    int c = ei[EE + e];
    float norm = g_dinv[r] * g_dinv[c];
    float4 v = ((const float4*)g_XW)[r * 16 + q];
    float* dst = &g_HL[c * 64 + q * 4];
    atomicAdd(dst + 0, norm * v.x);
    atomicAdd(dst + 1, norm * v.y);
    atomicAdd(dst + 2, norm * v.z);
    atomicAdd(dst + 3, norm * v.w);
}

// ---------------------------------------------------------------------------
// Main GEMM: out += aH * (Lsym @ R), plus (split 0 only) aL * (HL + selfloop + b)
// BM=128, BN=64, BK=32, 128 threads, 8x8 thread tile, split-K = 4.
// ---------------------------------------------------------------------------
__global__ void __launch_bounds__(128) k_gemm(const float* __restrict__ L,
                                              const float* __restrict__ bconv,
                                              const float* __restrict__ paL,
                                              const float* __restrict__ paH,
                                              float* __restrict__ out) {
    __shared__ float sAt[32][132];
    __shared__ float sB[32][68];

    const int m0    = blockIdx.x * 128;
    const int split = blockIdx.y;
    const int tid   = threadIdx.x;
    const int tx    = tid & 7;    // 0..7
    const int ty    = tid >> 3;   // 0..15

    float acc[8][8];
#pragma unroll
    for (int i = 0; i < 8; ++i)
#pragma unroll
        for (int j = 0; j < 8; ++j) acc[i][j] = 0.f;

    const int rA  = tid >> 3;     // 0..15 (A load row base)
    const int c4A = tid & 7;      // float4 col within 32-wide K chunk
    const int kB  = tid >> 4;     // 0..7  (B load row base)
    const int c4B = tid & 15;     // float4 col within 64

    const int k0base = split * 3072;

    for (int kt = 0; kt < 96; ++kt) {
        const int k0 = k0base + kt * 32;
        // load A tile 128x32, transpose into sAt[k][m]
#pragma unroll
        for (int it = 0; it < 8; ++it) {
            int rr = rA + it * 16;
            float4 v = *(const float4*)&L[(size_t)(m0 + rr) * NN + k0 + c4A * 4];
            sAt[c4A * 4 + 0][rr] = v.x;
            sAt[c4A * 4 + 1][rr] = v.y;
            sAt[c4A * 4 + 2][rr] = v.z;
            sAt[c4A * 4 + 3][rr] = v.w;
        }
        // load B tile 32x64 (R rows)
#pragma unroll
        for (int it = 0; it < 4; ++it) {
            int kr = kB + it * 8;
            float4 v = *(const float4*)&g_R[(size_t)(k0 + kr) * 64 + c4B * 4];
            *(float4*)&sB[kr][c4B * 4] = v;
        }
        __syncthreads();

#pragma unroll 8
        for (int kk = 0; kk < 32; ++kk) {
            float4 a0 = *(float4*)&sAt[kk][ty * 4];
            float4 a1 = *(float4*)&sAt[kk][64 + ty * 4];
            float4 b0 = *(float4*)&sB[kk][tx * 4];
            float4 b1 = *(float4*)&sB[kk][32 + tx * 4];
            float a[8] = {a0.x, a0.y, a0.z, a0.w, a1.x, a1.y, a1.z, a1.w};
            float b[8] = {b0.x, b0.y, b0.z, b0.w, b1.x, b1.y, b1.z, b1.w};
#pragma unroll
            for (int i = 0; i < 8; ++i)
#pragma unroll
                for (int j = 0; j < 8; ++j) acc[i][j] += a[i] * b[j];
        }
        __syncthreads();
    }

    const float aL = *paL;
    const float aH = *paH;

#pragma unroll
    for (int i = 0; i < 8; ++i) {
        int row = m0 + ((i < 4) ? (ty * 4 + i) : (64 + ty * 4 + i - 4));
        float di = g_dinv[row];
        float d2 = di * di;
#pragma unroll
        for (int j = 0; j < 8; ++j) {
            int col = (j < 4) ? (tx * 4 + j) : (32 + tx * 4 + j - 4);
            int idx = row * 64 + col;
            float v = aH * acc[i][j];
            if (split == 0)
                v += aL * (g_HL[idx] + d2 * g_XW[idx] + bconv[col]);
            atomicAdd(&out[idx], v);
        }
    }
}

// ---------------------------------------------------------------------------
extern "C" void kernel_launch(void* const* d_in, const int* in_sizes, int n_in,
                              void* d_out, int out_size) {
    const float* x   = (const float*)d_in[0];
    const int*   ei  = (const int*)d_in[1];
    const float* Ls  = (const float*)d_in[2];
    const float* Wh  = (const float*)d_in[3];
    const float* Wc  = (const float*)d_in[4];
    const float* bc  = (const float*)d_in[5];
    const float* aL  = (const float*)d_in[6];
    const float* aH  = (const float*)d_in[7];
    float* out = (float*)d_out;

    k_init<<<(NN * DD) / 256, 256>>>(out);
    k_deg<<<(EE + 255) / 256, 256>>>(ei);
    k_dinv<<<(NN + 255) / 256, 256>>>();
    k_xw<<<NN / 64, 256>>>(x, Wh, Wc);
    k_scatter<<<(EE * 16) / 256, 256>>>(ei);
    k_gemm<<<dim3(NN / 128, 4), 128>>>(Ls, bc, aL, aH, out);
}

// round 2
// speedup vs baseline: 1.0003x; 1.0003x over previous
#include <cuda_runtime.h>
#include <cstdint>

#define NN 12288
#define EE 196608
#define DD 64

// scratch (device globals — no allocation allowed)
__device__ float g_R[NN * DD];    // relu(x @ W_high^T)
__device__ float g_XW[NN * DD];   // x @ W_conv^T
__device__ float g_HL[NN * DD];   // scatter accumulation (edges only)
__device__ float g_dinv[NN];
__device__ int   g_deg[NN];

// ---------------------------------------------------------------------------
// init: zero HL and out, deg = 1 (self loop)
// ---------------------------------------------------------------------------
__global__ void k_init(float* __restrict__ out) {
    int i = blockIdx.x * 256 + threadIdx.x;   // grid sized to NN*DD exactly
    g_HL[i] = 0.0f;
    out[i]  = 0.0f;
    if (i < NN) g_deg[i] = 1;
}

// ---------------------------------------------------------------------------
// degree over edge targets
// ---------------------------------------------------------------------------
__global__ void k_deg(const int* __restrict__ ei) {
    int e = blockIdx.x * 256 + threadIdx.x;
    if (e < EE) atomicAdd(&g_deg[ei[EE + e]], 1);
}

__global__ void k_dinv() {
    int i = blockIdx.x * 256 + threadIdx.x;
    if (i < NN) g_dinv[i] = rsqrtf((float)g_deg[i]);
}

// ---------------------------------------------------------------------------
// R = relu(x @ Wh^T), XW = x @ Wc^T.  Block = 256 thr handles 64 nodes.
// SMEM exactly 48KB (3 x 64x64 f32). Reads: sXt contiguous, W uniform bcast.
// ---------------------------------------------------------------------------
__global__ void __launch_bounds__(256) k_xw(const float* __restrict__ x,
                                            const float* __restrict__ Wh,
                                            const float* __restrict__ Wc) {
    __shared__ float sXt[64][64];
    __shared__ float sWhT[64][64];
    __shared__ float sWcT[64][64];
    int tid = threadIdx.x;
    int nb  = blockIdx.x * 64;

#pragma unroll
    for (int it = 0; it < 4; ++it) {
        int idx = tid + it * 256;          // 0..1023 float4 slots
        int r   = idx >> 4;
        int c4  = idx & 15;
        float4 vx = *(const float4*)&x[(size_t)(nb + r) * 64 + c4 * 4];
        sXt[c4 * 4 + 0][r] = vx.x; sXt[c4 * 4 + 1][r] = vx.y;
        sXt[c4 * 4 + 2][r] = vx.z; sXt[c4 * 4 + 3][r] = vx.w;
        float4 vh = *(const float4*)&Wh[r * 64 + c4 * 4];
        sWhT[c4 * 4 + 0][r] = vh.x; sWhT[c4 * 4 + 1][r] = vh.y;
        sWhT[c4 * 4 + 2][r] = vh.z; sWhT[c4 * 4 + 3][r] = vh.w;
        float4 vc = *(const float4*)&Wc[r * 64 + c4 * 4];
        sWcT[c4 * 4 + 0][r] = vc.x; sWcT[c4 * 4 + 1][r] = vc.y;
        sWcT[c4 * 4 + 2][r] = vc.z; sWcT[c4 * 4 + 3][r] = vc.w;
    }
    __syncthreads();

    int n  = tid & 63;
    int cg = tid >> 6;                     // 0..3 -> 16-col group
    float aR[16], aC[16];
#pragma unroll
    for (int c = 0; c < 16; ++c) { aR[c] = 0.f; aC[c] = 0.f; }

#pragma unroll 4
    for (int k = 0; k < 64; ++k) {
        float xv = sXt[k][n];
#pragma unroll
        for (int c = 0; c < 16; ++c) {
            aR[c] += xv * sWhT[k][cg * 16 + c];
            aC[c] += xv * sWcT[k][cg * 16 + c];
        }
    }
    size_t base = (size_t)(nb + n) * 64 + cg * 16;
#pragma unroll
    for (int c = 0; c < 16; ++c) {
        g_R[base + c]  = fmaxf(aR[c], 0.0f);
        g_XW[base + c] = aC[c];
    }
}

// ---------------------------------------------------------------------------
// edge scatter: HL[col] += dinv[row]*dinv[col] * XW[row]
// one thread per (edge, float4-chunk): E*16 threads
// ---------------------------------------------------------------------------
__global__ void __launch_bounds__(256) k_scatter(const int* __restrict__ ei) {
    int t = blockIdx.x * 256 + threadIdx.x;   // grid sized to EE*16
    int e = t >> 4;
    int q = t & 15;
    int r = ei[e];
    int c = ei[EE + e];
    float norm = g_dinv[r] * g_dinv[c];
    float4 v = ((const float4*)g_XW)[r * 16 + q];
    float* dst = &g_HL[c * 64 + q * 4];
    atomicAdd(dst + 0, norm * v.x);
    atomicAdd(dst + 1, norm * v.y);
    atomicAdd(dst + 2, norm * v.z);
    atomicAdd(dst + 3, norm * v.w);
}

// ---------------------------------------------------------------------------
// Main GEMM: out += aH * (Lsym @ R), plus (split 0 only) aL * (HL + selfloop + b)
// BM=128, BN=64, BK=32, 128 threads, 8x8 thread tile, split-K = 4.
// ---------------------------------------------------------------------------
__global__ void __launch_bounds__(128) k_gemm(const float* __restrict__ L,
                                              const float* __restrict__ bconv,
                                              const float* __restrict__ paL,
                                              const float* __restrict__ paH,
                                              float* __restrict__ out) {
    __shared__ float sAt[32][132];
    __shared__ float sB[32][68];

    const int m0    = blockIdx.x * 128;
    const int split = blockIdx.y;
    const int tid   = threadIdx.x;
    const int tx    = tid & 7;    // 0..7
    const int ty    = tid >> 3;   // 0..15

    float acc[8][8];
#pragma unroll
    for (int i = 0; i < 8; ++i)
#pragma unroll
        for (int j = 0; j < 8; ++j) acc[i][j] = 0.f;

    const int rA  = tid >> 3;     // 0..15 (A load row base)
    const int c4A = tid & 7;      // float4 col within 32-wide K chunk
    const int kB  = tid >> 4;     // 0..7  (B load row base)
    const int c4B = tid & 15;     // float4 col within 64

    const int k0base = split * 3072;

    for (int kt = 0; kt < 96; ++kt) {
        const int k0 = k0base + kt * 32;
        // load A tile 128x32, transpose into sAt[k][m]
#pragma unroll
        for (int it = 0; it < 8; ++it) {
            int rr = rA + it * 16;
            float4 v = *(const float4*)&L[(size_t)(m0 + rr) * NN + k0 + c4A * 4];
            sAt[c4A * 4 + 0][rr] = v.x;
            sAt[c4A * 4 + 1][rr] = v.y;
            sAt[c4A * 4 + 2][rr] = v.z;
            sAt[c4A * 4 + 3][rr] = v.w;
        }
        // load B tile 32x64 (R rows)
#pragma unroll
        for (int it = 0; it < 4; ++it) {
            int kr = kB + it * 8;
            float4 v = *(const float4*)&g_R[(size_t)(k0 + kr) * 64 + c4B * 4];
            *(float4*)&sB[kr][c4B * 4] = v;
        }
        __syncthreads();

#pragma unroll 8
        for (int kk = 0; kk < 32; ++kk) {
            float4 a0 = *(float4*)&sAt[kk][ty * 4];
            float4 a1 = *(float4*)&sAt[kk][64 + ty * 4];
            float4 b0 = *(float4*)&sB[kk][tx * 4];
            float4 b1 = *(float4*)&sB[kk][32 + tx * 4];
            float a[8] = {a0.x, a0.y, a0.z, a0.w, a1.x, a1.y, a1.z, a1.w};
            float b[8] = {b0.x, b0.y, b0.z, b0.w, b1.x, b1.y, b1.z, b1.w};
#pragma unroll
            for (int i = 0; i < 8; ++i)
#pragma unroll
                for (int j = 0; j < 8; ++j) acc[i][j] += a[i] * b[j];
        }
        __syncthreads();
    }

    const float aL = *paL;
    const float aH = *paH;

#pragma unroll
    for (int i = 0; i < 8; ++i) {
        int row = m0 + ((i < 4) ? (ty * 4 + i) : (64 + ty * 4 + i - 4));
        float di = g_dinv[row];
        float d2 = di * di;
#pragma unroll
        for (int j = 0; j < 8; ++j) {
            int col = (j < 4) ? (tx * 4 + j) : (32 + tx * 4 + j - 4);
            int idx = row * 64 + col;
            float v = aH * acc[i][j];
            if (split == 0)
                v += aL * (g_HL[idx] + d2 * g_XW[idx] + bconv[col]);
            atomicAdd(&out[idx], v);
        }
    }
}

// ---------------------------------------------------------------------------
extern "C" void kernel_launch(void* const* d_in, const int* in_sizes, int n_in,
                              void* d_out, int out_size) {
    const float* x   = (const float*)d_in[0];
    const int*   ei  = (const int*)d_in[1];
    const float* Ls  = (const float*)d_in[2];
    const float* Wh  = (const float*)d_in[3];
    const float* Wc  = (const float*)d_in[4];
    const float* bc  = (const float*)d_in[5];
    const float* aL  = (const float*)d_in[6];
    const float* aH  = (const float*)d_in[7];
    float* out = (float*)d_out;

    k_init<<<(NN * DD) / 256, 256>>>(out);
    k_deg<<<(EE + 255) / 256, 256>>>(ei);
    k_dinv<<<(NN + 255) / 256, 256>>>();
    k_xw<<<NN / 64, 256>>>(x, Wh, Wc);
    k_scatter<<<(EE * 16) / 256, 256>>>(ei);
    k_gemm<<<dim3(NN / 128, 4), 128>>>(Ls, bc, aL, aH, out);
}

// round 4
// speedup vs baseline: 1.8867x; 1.8862x over previous
#include <cuda_runtime.h>
#include <cstdint>

#define NN 12288
#define EE 196608
#define DD 64
#define NCH 384                  // K chunks of 32
#define A_ROW_F 36               // padded floats per A smem row (128B data + 16B pad)
#define B_ROW_F 72               // padded floats per B smem row (256B data + 32B pad)
#define A_STAGE_B (128 * A_ROW_F * 4)   // 18432
#define B_STAGE_B (32 * B_ROW_F * 4)    //  9216
#define STAGE_B (A_STAGE_B + B_STAGE_B) // 27648
#define SM_TOTAL (3 * STAGE_B)          // 82944

// scratch (device globals — no allocation allowed)
__device__ float g_R[NN * DD];    // relu(x @ Wh^T), tf32-rounded, row-major [node][64]
__device__ float g_XW[NN * DD];   // x @ Wc^T (exact fp32)
__device__ float g_HL[NN * DD];   // edge scatter accumulation
__device__ float g_dinv[NN];
__device__ int   g_deg[NN];

// ---------------------------------------------------------------------------
__device__ __forceinline__ uint32_t smem_u32(const void* p) {
    uint32_t a;
    asm("{ .reg .u64 t; cvta.to.shared.u64 t, %1; cvt.u32.u64 %0, t; }"
        : "=r"(a) : "l"(p));
    return a;
}

__device__ __forceinline__ uint32_t f2tf32(float x) {
    uint32_t t;
    asm("cvt.rna.tf32.f32 %0, %1;" : "=r"(t) : "f"(x));
    return t;
}

__device__ __forceinline__ void cp16(uint32_t dst, const void* src) {
    asm volatile("cp.async.cg.shared.global [%0], [%1], 16;"
                 :: "r"(dst), "l"(__cvta_generic_to_global(src)) : "memory");
}
#define CP_COMMIT() asm volatile("cp.async.commit_group;" ::: "memory")
#define CP_WAIT1()  asm volatile("cp.async.wait_group 1;"  ::: "memory")

__device__ __forceinline__ void mma_tf32(float* c, const uint32_t* a, const uint32_t* b) {
    asm volatile(
        "mma.sync.aligned.m16n8k8.row.col.f32.tf32.tf32.f32 "
        "{%0,%1,%2,%3}, {%4,%5,%6,%7}, {%8,%9}, {%0,%1,%2,%3};"
        : "+f"(c[0]), "+f"(c[1]), "+f"(c[2]), "+f"(c[3])
        : "r"(a[0]), "r"(a[1]), "r"(a[2]), "r"(a[3]), "r"(b[0]), "r"(b[1]));
}

// ---------------------------------------------------------------------------
// init: zero HL, deg = 1 (self loop)
// ---------------------------------------------------------------------------
__global__ void k_init() {
    int i = blockIdx.x * 256 + threadIdx.x;   // grid = NN*DD/256
    g_HL[i] = 0.0f;
    if (i < NN) g_deg[i] = 1;
}

__global__ void k_deg(const int* __restrict__ ei) {
    int e = blockIdx.x * 256 + threadIdx.x;
    if (e < EE) atomicAdd(&g_deg[ei[EE + e]], 1);
}

__global__ void k_dinv() {
    int i = blockIdx.x * 256 + threadIdx.x;
    if (i < NN) g_dinv[i] = rsqrtf((float)g_deg[i]);
}

// ---------------------------------------------------------------------------
// R = tf32(relu(x @ Wh^T)) [NN][64],  XW = x @ Wc^T [NN][64]
// ---------------------------------------------------------------------------
__global__ void __launch_bounds__(256) k_xw(const float* __restrict__ x,
                                            const float* __restrict__ Wh,
                                            const float* __restrict__ Wc) {
    __shared__ float sXt[64][64];
    __shared__ float sWhT[64][64];
    __shared__ float sWcT[64][64];
    int tid = threadIdx.x;
    int nb  = blockIdx.x * 64;

#pragma unroll
    for (int it = 0; it < 4; ++it) {
        int idx = tid + it * 256;
        int r   = idx >> 4;
        int c4  = idx & 15;
        float4 vx = *(const float4*)&x[(size_t)(nb + r) * 64 + c4 * 4];
        sXt[c4 * 4 + 0][r] = vx.x; sXt[c4 * 4 + 1][r] = vx.y;
        sXt[c4 * 4 + 2][r] = vx.z; sXt[c4 * 4 + 3][r] = vx.w;
        float4 vh = *(const float4*)&Wh[r * 64 + c4 * 4];
        sWhT[c4 * 4 + 0][r] = vh.x; sWhT[c4 * 4 + 1][r] = vh.y;
        sWhT[c4 * 4 + 2][r] = vh.z; sWhT[c4 * 4 + 3][r] = vh.w;
        float4 vc = *(const float4*)&Wc[r * 64 + c4 * 4];
        sWcT[c4 * 4 + 0][r] = vc.x; sWcT[c4 * 4 + 1][r] = vc.y;
        sWcT[c4 * 4 + 2][r] = vc.z; sWcT[c4 * 4 + 3][r] = vc.w;
    }
    __syncthreads();

    int n  = tid & 63;
    int cg = tid >> 6;
    float aR[16], aC[16];
#pragma unroll
    for (int c = 0; c < 16; ++c) { aR[c] = 0.f; aC[c] = 0.f; }

#pragma unroll 4
    for (int k = 0; k < 64; ++k) {
        float xv = sXt[k][n];
#pragma unroll
        for (int c = 0; c < 16; ++c) {
            aR[c] += xv * sWhT[k][cg * 16 + c];
            aC[c] += xv * sWcT[k][cg * 16 + c];
        }
    }
    size_t base = (size_t)(nb + n) * 64 + cg * 16;
#pragma unroll
    for (int c = 0; c < 16; ++c) {
        g_R[base + c]  = __uint_as_float(f2tf32(fmaxf(aR[c], 0.0f)));
        g_XW[base + c] = aC[c];
    }
}

// ---------------------------------------------------------------------------
// edge scatter: HL[col] += dinv[row]*dinv[col] * XW[row]
// ---------------------------------------------------------------------------
__global__ void __launch_bounds__(256) k_scatter(const int* __restrict__ ei) {
    int t = blockIdx.x * 256 + threadIdx.x;   // grid = EE*16/256
    int e = t >> 4;
    int q = t & 15;
    int r = ei[e];
    int c = ei[EE + e];
    float norm = g_dinv[r] * g_dinv[c];
    float4 v = ((const float4*)g_XW)[r * 16 + q];
    float* dst = &g_HL[c * 64 + q * 4];
    atomicAdd(dst + 0, norm * v.x);
    atomicAdd(dst + 1, norm * v.y);
    atomicAdd(dst + 2, norm * v.z);
    atomicAdd(dst + 3, norm * v.w);
}

// ---------------------------------------------------------------------------
// Main GEMM via mma.sync tf32: out = aH*(Lsym@R) + aL*(HL + selfloop + b)
// 96 CTAs, BM=128, BN=64, BK=32, 3-stage cp.async pipeline,
// 8 warps in 4x2 grid, warp tile 32x32, m16n8k8 fragments.
// ---------------------------------------------------------------------------
__global__ void __launch_bounds__(256, 1) k_gemm(const float* __restrict__ L,
                                                 const float* __restrict__ bconv,
                                                 const float* __restrict__ paL,
                                                 const float* __restrict__ paH,
                                                 float* __restrict__ out) {
    extern __shared__ char smem[];
    const uint32_t sb = smem_u32(smem);
    const int tid  = threadIdx.x;
    const int lane = tid & 31;
    const int w    = tid >> 5;
    const int wm   = w >> 1;          // 0..3 (M)
    const int wn   = w & 1;           // 0..1 (N)
    const int g    = lane >> 2;       // groupID 0..7
    const int t    = lane & 3;        // threadID_in_group 0..3
    const int m0   = blockIdx.x * 128;

    float acc[2][4][4];
#pragma unroll
    for (int mi = 0; mi < 2; ++mi)
#pragma unroll
        for (int ni = 0; ni < 4; ++ni)
#pragma unroll
            for (int q = 0; q < 4; ++q) acc[mi][ni][q] = 0.f;

    // per-thread copy coords (fixed)
    const int amr = tid >> 3, amc = tid & 7;        // A: 2 rows per thread (it*256)
    const int bkr = tid >> 4, bkc = tid & 15;       // B: 2 rows per thread

    auto COPY = [&](int ct, int s) {
        uint32_t aB = sb + s * STAGE_B;
        uint32_t bB = aB + A_STAGE_B;
        const float* Ap = L + (size_t)m0 * NN + ct * 32;
#pragma unroll
        for (int i = 0; i < 4; ++i) {
            int m = amr + i * 32;
            cp16(aB + m * (A_ROW_F * 4) + amc * 16, Ap + (size_t)m * NN + amc * 4);
        }
        const float* Bp = g_R + (size_t)ct * 32 * 64;
#pragma unroll
        for (int i = 0; i < 2; ++i) {
            int k = bkr + i * 16;
            cp16(bB + k * (B_ROW_F * 4) + bkc * 16, Bp + (size_t)k * 64 + bkc * 4);
        }
    };

    COPY(0, 0); CP_COMMIT();
    COPY(1, 1); CP_COMMIT();

    for (int ct = 0; ct < NCH; ++ct) {
        CP_WAIT1();
        __syncthreads();
        if (ct + 2 < NCH) COPY(ct + 2, (ct + 2) % 3);
        CP_COMMIT();

        const float* sA = (const float*)(smem + (ct % 3) * STAGE_B);
        const float* sB = (const float*)(smem + (ct % 3) * STAGE_B + A_STAGE_B);

#pragma unroll
        for (int ks = 0; ks < 4; ++ks) {
            uint32_t a[2][4], b[4][2];
            int kc = ks * 8 + t;
#pragma unroll
            for (int mi = 0; mi < 2; ++mi) {
                int r = wm * 32 + mi * 16 + g;
                a[mi][0] = f2tf32(sA[r * A_ROW_F + kc]);
                a[mi][1] = f2tf32(sA[(r + 8) * A_ROW_F + kc]);
                a[mi][2] = f2tf32(sA[r * A_ROW_F + kc + 4]);
                a[mi][3] = f2tf32(sA[(r + 8) * A_ROW_F + kc + 4]);
            }
#pragma unroll
            for (int ni = 0; ni < 4; ++ni) {
                int n = wn * 32 + ni * 8 + g;
                b[ni][0] = __float_as_uint(sB[kc * B_ROW_F + n]);
                b[ni][1] = __float_as_uint(sB[(kc + 4) * B_ROW_F + n]);
            }
#pragma unroll
            for (int mi = 0; mi < 2; ++mi)
#pragma unroll
                for (int ni = 0; ni < 4; ++ni)
                    mma_tf32(acc[mi][ni], a[mi], b[ni]);
        }
    }

    // epilogue: fuse exact-fp32 low-pass branch, plain stores
    const float aLv = *paL, aHv = *paH;
#pragma unroll
    for (int mi = 0; mi < 2; ++mi) {
#pragma unroll
        for (int half = 0; half < 2; ++half) {
            int row = m0 + wm * 32 + mi * 16 + half * 8 + g;
            float di = g_dinv[row];
            float d2 = di * di;
            size_t rb = (size_t)row * 64;
#pragma unroll
            for (int ni = 0; ni < 4; ++ni) {
                int c = wn * 32 + ni * 8 + t * 2;
                float2 hl = *(const float2*)&g_HL[rb + c];
                float2 xw = *(const float2*)&g_XW[rb + c];
                float2 bb = *(const float2*)&bconv[c];
                float2 o;
                o.x = aHv * acc[mi][ni][half * 2 + 0] + aLv * (hl.x + d2 * xw.x + bb.x);
                o.y = aHv * acc[mi][ni][half * 2 + 1] + aLv * (hl.y + d2 * xw.y + bb.y);
                *(float2*)&out[rb + c] = o;
            }
        }
    }
}

// ---------------------------------------------------------------------------
extern "C" void kernel_launch(void* const* d_in, const int* in_sizes, int n_in,
                              void* d_out, int out_size) {
    const float* x  = (const float*)d_in[0];
    const int*   ei = (const int*)d_in[1];
    const float* Ls = (const float*)d_in[2];
    const float* Wh = (const float*)d_in[3];
    const float* Wc = (const float*)d_in[4];
    const float* bc = (const float*)d_in[5];
    const float* aL = (const float*)d_in[6];
    const float* aH = (const float*)d_in[7];
    float* out = (float*)d_out;

    cudaFuncSetAttribute(k_gemm, cudaFuncAttributeMaxDynamicSharedMemorySize, SM_TOTAL);

    k_init<<<(NN * DD) / 256, 256>>>();
    k_deg<<<(EE + 255) / 256, 256>>>(ei);
    k_dinv<<<(NN + 255) / 256, 256>>>();
    k_xw<<<NN / 64, 256>>>(x, Wh, Wc);
    k_scatter<<<(EE * 16) / 256, 256>>>(ei);
    k_gemm<<<96, 256, SM_TOTAL>>>(Ls, bc, aL, aH, out);
}

// round 5
// speedup vs baseline: 2.7442x; 1.4545x over previous
#include <cuda_runtime.h>
#include <cstdint>

#define NN 12288
#define EE 196608
#define DD 64
#define NCH 384                  // total K chunks of 32
#define KSPLIT 3
#define CHPS (NCH / KSPLIT)      // 128 chunks per split
#define A_ROW_F 36               // padded floats per A smem row (128B data + 16B pad)
#define B_ROW_F 72               // padded floats per B smem row (256B data + 32B pad)
#define A_STAGE_B (128 * A_ROW_F * 4)   // 18432
#define B_STAGE_B (32 * B_ROW_F * 4)    //  9216
#define STAGE_B (A_STAGE_B + B_STAGE_B) // 27648
#define SM_TOTAL (3 * STAGE_B)          // 82944

// scratch (device globals — no allocation allowed)
__device__ float g_R[NN * DD];    // relu(x @ Wh^T), tf32-rounded, row-major [node][64]
__device__ float g_XW[NN * DD];   // x @ Wc^T (exact fp32)
__device__ float g_HL[NN * DD];   // edge scatter accumulation
__device__ float g_dinv[NN];
__device__ int   g_deg[NN];

// ---------------------------------------------------------------------------
__device__ __forceinline__ uint32_t smem_u32(const void* p) {
    uint32_t a;
    asm("{ .reg .u64 t; cvta.to.shared.u64 t, %1; cvt.u32.u64 %0, t; }"
        : "=r"(a) : "l"(p));
    return a;
}

__device__ __forceinline__ uint32_t f2tf32(float x) {
    uint32_t t;
    asm("cvt.rna.tf32.f32 %0, %1;" : "=r"(t) : "f"(x));
    return t;
}

__device__ __forceinline__ void cp16(uint32_t dst, const void* src) {
    asm volatile("cp.async.cg.shared.global [%0], [%1], 16;"
                 :: "r"(dst), "l"(__cvta_generic_to_global(src)) : "memory");
}
#define CP_COMMIT() asm volatile("cp.async.commit_group;" ::: "memory")
#define CP_WAIT1()  asm volatile("cp.async.wait_group 1;"  ::: "memory")

__device__ __forceinline__ void mma_tf32(float* c, const uint32_t* a, const uint32_t* b) {
    asm volatile(
        "mma.sync.aligned.m16n8k8.row.col.f32.tf32.tf32.f32 "
        "{%0,%1,%2,%3}, {%4,%5,%6,%7}, {%8,%9}, {%0,%1,%2,%3};"
        : "+f"(c[0]), "+f"(c[1]), "+f"(c[2]), "+f"(c[3])
        : "r"(a[0]), "r"(a[1]), "r"(a[2]), "r"(a[3]), "r"(b[0]), "r"(b[1]));
}

// ---------------------------------------------------------------------------
// init: zero HL and out, deg = 1 (self loop)
// ---------------------------------------------------------------------------
__global__ void k_init(float* __restrict__ out) {
    int i = blockIdx.x * 256 + threadIdx.x;   // grid = NN*DD/256
    g_HL[i] = 0.0f;
    out[i]  = 0.0f;
    if (i < NN) g_deg[i] = 1;
}

__global__ void k_deg(const int* __restrict__ ei) {
    int e = blockIdx.x * 256 + threadIdx.x;
    if (e < EE) atomicAdd(&g_deg[ei[EE + e]], 1);
}

__global__ void k_dinv() {
    int i = blockIdx.x * 256 + threadIdx.x;
    if (i < NN) g_dinv[i] = rsqrtf((float)g_deg[i]);
}

// ---------------------------------------------------------------------------
// R = tf32(relu(x @ Wh^T)) [NN][64],  XW = x @ Wc^T [NN][64]
// ---------------------------------------------------------------------------
__global__ void __launch_bounds__(256) k_xw(const float* __restrict__ x,
                                            const float* __restrict__ Wh,
                                            const float* __restrict__ Wc) {
    __shared__ float sXt[64][64];
    __shared__ float sWhT[64][64];
    __shared__ float sWcT[64][64];
    int tid = threadIdx.x;
    int nb  = blockIdx.x * 64;

#pragma unroll
    for (int it = 0; it < 4; ++it) {
        int idx = tid + it * 256;
        int r   = idx >> 4;
        int c4  = idx & 15;
        float4 vx = *(const float4*)&x[(size_t)(nb + r) * 64 + c4 * 4];
        sXt[c4 * 4 + 0][r] = vx.x; sXt[c4 * 4 + 1][r] = vx.y;
        sXt[c4 * 4 + 2][r] = vx.z; sXt[c4 * 4 + 3][r] = vx.w;
        float4 vh = *(const float4*)&Wh[r * 64 + c4 * 4];
        sWhT[c4 * 4 + 0][r] = vh.x; sWhT[c4 * 4 + 1][r] = vh.y;
        sWhT[c4 * 4 + 2][r] = vh.z; sWhT[c4 * 4 + 3][r] = vh.w;
        float4 vc = *(const float4*)&Wc[r * 64 + c4 * 4];
        sWcT[c4 * 4 + 0][r] = vc.x; sWcT[c4 * 4 + 1][r] = vc.y;
        sWcT[c4 * 4 + 2][r] = vc.z; sWcT[c4 * 4 + 3][r] = vc.w;
    }
    __syncthreads();

    int n  = tid & 63;
    int cg = tid >> 6;
    float aR[16], aC[16];
#pragma unroll
    for (int c = 0; c < 16; ++c) { aR[c] = 0.f; aC[c] = 0.f; }

#pragma unroll 4
    for (int k = 0; k < 64; ++k) {
        float xv = sXt[k][n];
#pragma unroll
        for (int c = 0; c < 16; ++c) {
            aR[c] += xv * sWhT[k][cg * 16 + c];
            aC[c] += xv * sWcT[k][cg * 16 + c];
        }
    }
    size_t base = (size_t)(nb + n) * 64 + cg * 16;
#pragma unroll
    for (int c = 0; c < 16; ++c) {
        g_R[base + c]  = __uint_as_float(f2tf32(fmaxf(aR[c], 0.0f)));
        g_XW[base + c] = aC[c];
    }
}

// ---------------------------------------------------------------------------
// edge scatter: HL[col] += dinv[row]*dinv[col] * XW[row]
// ---------------------------------------------------------------------------
__global__ void __launch_bounds__(256) k_scatter(const int* __restrict__ ei) {
    int t = blockIdx.x * 256 + threadIdx.x;   // grid = EE*16/256
    int e = t >> 4;
    int q = t & 15;
    int r = ei[e];
    int c = ei[EE + e];
    float norm = g_dinv[r] * g_dinv[c];
    float4 v = ((const float4*)g_XW)[r * 16 + q];
    float* dst = &g_HL[c * 64 + q * 4];
    atomicAdd(dst + 0, norm * v.x);
    atomicAdd(dst + 1, norm * v.y);
    atomicAdd(dst + 2, norm * v.z);
    atomicAdd(dst + 3, norm * v.w);
}

// ---------------------------------------------------------------------------
// Main GEMM via mma.sync tf32, split-K=3: out += aH*(Lsym@R)_partial
// (+ split 0: aL*(HL + selfloop + b)).  Grid 96x3 = 288 CTAs, 2 resident/SM.
// BM=128, BN=64, BK=32, 3-stage cp.async, 8 warps 4x2, warp tile 32x32.
// ---------------------------------------------------------------------------
__global__ void __launch_bounds__(256, 2) k_gemm(const float* __restrict__ L,
                                                 const float* __restrict__ bconv,
                                                 const float* __restrict__ paL,
                                                 const float* __restrict__ paH,
                                                 float* __restrict__ out) {
    extern __shared__ char smem[];
    const uint32_t sb = smem_u32(smem);
    const int tid  = threadIdx.x;
    const int lane = tid & 31;
    const int w    = tid >> 5;
    const int wm   = w >> 1;          // 0..3 (M)
    const int wn   = w & 1;           // 0..1 (N)
    const int g    = lane >> 2;       // groupID 0..7
    const int t    = lane & 3;        // threadID_in_group 0..3
    const int m0   = blockIdx.x * 128;
    const int cb   = blockIdx.y * CHPS;   // chunk base for this split

    float acc[2][4][4];
#pragma unroll
    for (int mi = 0; mi < 2; ++mi)
#pragma unroll
        for (int ni = 0; ni < 4; ++ni)
#pragma unroll
            for (int q = 0; q < 4; ++q) acc[mi][ni][q] = 0.f;

    const int amr = tid >> 3, amc = tid & 7;
    const int bkr = tid >> 4, bkc = tid & 15;

    auto COPY = [&](int ct, int s) {
        uint32_t aB = sb + s * STAGE_B;
        uint32_t bB = aB + A_STAGE_B;
        const float* Ap = L + (size_t)m0 * NN + (cb + ct) * 32;
#pragma unroll
        for (int i = 0; i < 4; ++i) {
            int m = amr + i * 32;
            cp16(aB + m * (A_ROW_F * 4) + amc * 16, Ap + (size_t)m * NN + amc * 4);
        }
        const float* Bp = g_R + (size_t)(cb + ct) * 32 * 64;
#pragma unroll
        for (int i = 0; i < 2; ++i) {
            int k = bkr + i * 16;
            cp16(bB + k * (B_ROW_F * 4) + bkc * 16, Bp + (size_t)k * 64 + bkc * 4);
        }
    };

    COPY(0, 0); CP_COMMIT();
    COPY(1, 1); CP_COMMIT();

    for (int ct = 0; ct < CHPS; ++ct) {
        CP_WAIT1();
        __syncthreads();
        if (ct + 2 < CHPS) COPY(ct + 2, (ct + 2) % 3);
        CP_COMMIT();

        const float* sA = (const float*)(smem + (ct % 3) * STAGE_B);
        const float* sB = (const float*)(smem + (ct % 3) * STAGE_B + A_STAGE_B);

#pragma unroll
        for (int ks = 0; ks < 4; ++ks) {
            uint32_t a[2][4], b[4][2];
            int kc = ks * 8 + t;
#pragma unroll
            for (int mi = 0; mi < 2; ++mi) {
                int r = wm * 32 + mi * 16 + g;
                a[mi][0] = f2tf32(sA[r * A_ROW_F + kc]);
                a[mi][1] = f2tf32(sA[(r + 8) * A_ROW_F + kc]);
                a[mi][2] = f2tf32(sA[r * A_ROW_F + kc + 4]);
                a[mi][3] = f2tf32(sA[(r + 8) * A_ROW_F + kc + 4]);
            }
#pragma unroll
            for (int ni = 0; ni < 4; ++ni) {
                int n = wn * 32 + ni * 8 + g;
                b[ni][0] = __float_as_uint(sB[kc * B_ROW_F + n]);
                b[ni][1] = __float_as_uint(sB[(kc + 4) * B_ROW_F + n]);
            }
#pragma unroll
            for (int mi = 0; mi < 2; ++mi)
#pragma unroll
                for (int ni = 0; ni < 4; ++ni)
                    mma_tf32(acc[mi][ni], a[mi], b[ni]);
        }
    }

    // epilogue: atomic accumulate; split 0 adds the exact fp32 low-pass branch
    const float aLv = *paL, aHv = *paH;
    const bool  z0  = (blockIdx.y == 0);
#pragma unroll
    for (int mi = 0; mi < 2; ++mi) {
#pragma unroll
        for (int half = 0; half < 2; ++half) {
            int row = m0 + wm * 32 + mi * 16 + half * 8 + g;
            float di = g_dinv[row];
            float d2 = di * di;
            size_t rb = (size_t)row * 64;
#pragma unroll
            for (int ni = 0; ni < 4; ++ni) {
                int c = wn * 32 + ni * 8 + t * 2;
                float vx = aHv * acc[mi][ni][half * 2 + 0];
                float vy = aHv * acc[mi][ni][half * 2 + 1];
                if (z0) {
                    float2 hl = *(const float2*)&g_HL[rb + c];
                    float2 xw = *(const float2*)&g_XW[rb + c];
                    float2 bb = *(const float2*)&bconv[c];
                    vx += aLv * (hl.x + d2 * xw.x + bb.x);
                    vy += aLv * (hl.y + d2 * xw.y + bb.y);
                }
                atomicAdd(&out[rb + c + 0], vx);
                atomicAdd(&out[rb + c + 1], vy);
            }
        }
    }
}

// ---------------------------------------------------------------------------
extern "C" void kernel_launch(void* const* d_in, const int* in_sizes, int n_in,
                              void* d_out, int out_size) {
    const float* x  = (const float*)d_in[0];
    const int*   ei = (const int*)d_in[1];
    const float* Ls = (const float*)d_in[2];
    const float* Wh = (const float*)d_in[3];
    const float* Wc = (const float*)d_in[4];
    const float* bc = (const float*)d_in[5];
    const float* aL = (const float*)d_in[6];
    const float* aH = (const float*)d_in[7];
    float* out = (float*)d_out;

    cudaFuncSetAttribute(k_gemm, cudaFuncAttributeMaxDynamicSharedMemorySize, SM_TOTAL);

    k_init<<<(NN * DD) / 256, 256>>>(out);
    k_deg<<<(EE + 255) / 256, 256>>>(ei);
    k_dinv<<<(NN + 255) / 256, 256>>>();
    k_xw<<<NN / 64, 256>>>(x, Wh, Wc);
    k_scatter<<<(EE * 16) / 256, 256>>>(ei);
    k_gemm<<<dim3(96, KSPLIT), 256, SM_TOTAL>>>(Ls, bc, aL, aH, out);
}

// round 6
// speedup vs baseline: 3.1180x; 1.1362x over previous
#include <cuda_runtime.h>
#include <cstdint>

#define NN 12288
#define EE 196608
#define DD 64
#define KSPLIT 3
#define CHPS 32                   // chunks of BK=128 per split (96 total / 3)
#define A_ROW_F 132               // 128 floats + 4 pad = 528 B
#define B_ROW_F 72                // 64 floats + 8 pad = 288 B
#define A_STAGE_B (128 * A_ROW_F * 4)   // 67584
#define B_STAGE_B (128 * B_ROW_F * 4)   // 36864
#define STAGE_B (A_STAGE_B + B_STAGE_B) // 104448
#define SM_GEMM (2 * STAGE_B)           // 208896
#define XW_ROW_F 68
#define SM_XW (2 * 128 * XW_ROW_F * 4)  // 69632

// scratch (device globals — no allocation allowed)
__device__ float g_R[NN * DD];    // relu(x @ Wh^T), tf32-rounded, [node][64]
__device__ float g_XW[NN * DD];   // x @ Wc^T (tf32 MMA), [node][64]
__device__ float g_dinv[NN];
__device__ int   g_deg[NN];

// ---------------------------------------------------------------------------
__device__ __forceinline__ uint32_t smem_u32(const void* p) {
    uint32_t a;
    asm("{ .reg .u64 t; cvta.to.shared.u64 t, %1; cvt.u32.u64 %0, t; }"
        : "=r"(a) : "l"(p));
    return a;
}

__device__ __forceinline__ uint32_t f2tf32(float x) {
    uint32_t t;
    asm("cvt.rna.tf32.f32 %0, %1;" : "=r"(t) : "f"(x));
    return t;
}

__device__ __forceinline__ void cp16(uint32_t dst, const void* src) {
    asm volatile("cp.async.cg.shared.global [%0], [%1], 16;"
                 :: "r"(dst), "l"(__cvta_generic_to_global(src)) : "memory");
}
#define CP_COMMIT() asm volatile("cp.async.commit_group;" ::: "memory")
#define CP_WAIT1()  asm volatile("cp.async.wait_group 1;"  ::: "memory")
#define CP_WAIT0()  asm volatile("cp.async.wait_group 0;"  ::: "memory")

__device__ __forceinline__ void mma_tf32(float* c, const uint32_t* a, const uint32_t* b) {
    asm volatile(
        "mma.sync.aligned.m16n8k8.row.col.f32.tf32.tf32.f32 "
        "{%0,%1,%2,%3}, {%4,%5,%6,%7}, {%8,%9}, {%0,%1,%2,%3};"
        : "+f"(c[0]), "+f"(c[1]), "+f"(c[2]), "+f"(c[3])
        : "r"(a[0]), "r"(a[1]), "r"(a[2]), "r"(a[3]), "r"(b[0]), "r"(b[1]));
}

__device__ __forceinline__ void red2(float* p, float x, float y) {
    asm volatile("red.global.add.v2.f32 [%0], {%1,%2};"
                 :: "l"(__cvta_generic_to_global(p)), "f"(x), "f"(y) : "memory");
}
__device__ __forceinline__ void red4(float* p, float x, float y, float z, float w) {
    asm volatile("red.global.add.v4.f32 [%0], {%1,%2,%3,%4};"
                 :: "l"(__cvta_generic_to_global(p)), "f"(x), "f"(y), "f"(z), "f"(w)
                 : "memory");
}

// ---------------------------------------------------------------------------
__global__ void k_init(float* __restrict__ out) {
    int i = blockIdx.x * 256 + threadIdx.x;   // grid = NN*DD/256
    out[i] = 0.0f;
    if (i < NN) g_deg[i] = 1;
}

__global__ void k_deg(const int* __restrict__ ei) {
    int e = blockIdx.x * 256 + threadIdx.x;
    if (e < EE) atomicAdd(&g_deg[ei[EE + e]], 1);
}

__global__ void k_dinv() {
    int i = blockIdx.x * 256 + threadIdx.x;
    if (i < NN) g_dinv[i] = rsqrtf((float)g_deg[i]);
}

// ---------------------------------------------------------------------------
// Fused projections via tensor cores: [R | XW] = x @ [Wh ; Wc]^T
// M=12288 (128/CTA, 96 CTAs), N=128, K=64 one-shot.
// ---------------------------------------------------------------------------
__global__ void __launch_bounds__(256) k_xw(const float* __restrict__ x,
                                            const float* __restrict__ Wh,
                                            const float* __restrict__ Wc) {
    extern __shared__ char smem[];
    const uint32_t sb = smem_u32(smem);
    const float* sX = (const float*)smem;
    const float* sW = (const float*)(smem + 128 * XW_ROW_F * 4);
    const uint32_t sWb = sb + 128 * XW_ROW_F * 4;

    const int tid  = threadIdx.x;
    const int lane = tid & 31;
    const int w    = tid >> 5;
    const int wm   = w >> 1;
    const int wn   = w & 1;
    const int g    = lane >> 2;
    const int t    = lane & 3;
    const int m0   = blockIdx.x * 128;

    // load x tile [128][64] and stacked W [128][64]
#pragma unroll
    for (int i = 0; i < 8; ++i) {
        int idx = tid + i * 256;
        int r = idx >> 4, c = idx & 15;
        cp16(sb + r * (XW_ROW_F * 4) + c * 16, x + (size_t)(m0 + r) * 64 + c * 4);
        const float* wsrc = (r < 64) ? (Wh + (size_t)r * 64 + c * 4)
                                     : (Wc + (size_t)(r - 64) * 64 + c * 4);
        cp16(sWb + r * (XW_ROW_F * 4) + c * 16, wsrc);
    }
    CP_COMMIT();
    CP_WAIT0();
    __syncthreads();

    float acc[2][8][4];
#pragma unroll
    for (int mi = 0; mi < 2; ++mi)
#pragma unroll
        for (int ni = 0; ni < 8; ++ni)
#pragma unroll
            for (int q = 0; q < 4; ++q) acc[mi][ni][q] = 0.f;

#pragma unroll
    for (int ks = 0; ks < 8; ++ks) {
        int kc = ks * 8 + t;
        uint32_t a[2][4], b[8][2];
#pragma unroll
        for (int mi = 0; mi < 2; ++mi) {
            int r = wm * 32 + mi * 16 + g;
            a[mi][0] = f2tf32(sX[r * XW_ROW_F + kc]);
            a[mi][1] = f2tf32(sX[(r + 8) * XW_ROW_F + kc]);
            a[mi][2] = f2tf32(sX[r * XW_ROW_F + kc + 4]);
            a[mi][3] = f2tf32(sX[(r + 8) * XW_ROW_F + kc + 4]);
        }
#pragma unroll
        for (int ni = 0; ni < 8; ++ni) {
            int n = wn * 64 + ni * 8 + g;
            b[ni][0] = f2tf32(sW[n * XW_ROW_F + kc]);
            b[ni][1] = f2tf32(sW[n * XW_ROW_F + kc + 4]);
        }
#pragma unroll
        for (int mi = 0; mi < 2; ++mi)
#pragma unroll
            for (int ni = 0; ni < 8; ++ni)
                mma_tf32(acc[mi][ni], a[mi], b[ni]);
    }

    // wn==0 warps hold R cols (relu + tf32 round); wn==1 warps hold XW cols
#pragma unroll
    for (int mi = 0; mi < 2; ++mi) {
#pragma unroll
        for (int half = 0; half < 2; ++half) {
            int row = m0 + wm * 32 + mi * 16 + half * 8 + g;
            size_t rb = (size_t)row * 64;
#pragma unroll
            for (int ni = 0; ni < 8; ++ni) {
                int c = ni * 8 + t * 2;
                float v0 = acc[mi][ni][half * 2 + 0];
                float v1 = acc[mi][ni][half * 2 + 1];
                if (wn == 0) {
                    float2 o;
                    o.x = __uint_as_float(f2tf32(fmaxf(v0, 0.f)));
                    o.y = __uint_as_float(f2tf32(fmaxf(v1, 0.f)));
                    *(float2*)&g_R[rb + c] = o;
                } else {
                    float2 o; o.x = v0; o.y = v1;
                    *(float2*)&g_XW[rb + c] = o;
                }
            }
        }
    }
}

// ---------------------------------------------------------------------------
// edge scatter straight into out: out[col] += aL * dinv[r]*dinv[c] * XW[row]
// ---------------------------------------------------------------------------
__global__ void __launch_bounds__(256) k_scatter(const int* __restrict__ ei,
                                                 const float* __restrict__ paL,
                                                 float* __restrict__ out) {
    int tt = blockIdx.x * 256 + threadIdx.x;   // grid = EE*16/256
    int e = tt >> 4;
    int q = tt & 15;
    int r = ei[e];
    int c = ei[EE + e];
    float norm = (*paL) * g_dinv[r] * g_dinv[c];
    float4 v = ((const float4*)g_XW)[r * 16 + q];
    red4(&out[c * 64 + q * 4], norm * v.x, norm * v.y, norm * v.z, norm * v.w);
}

// ---------------------------------------------------------------------------
// Main GEMM via mma.sync tf32, split-K=3, BK=128 (512B/row DRAM bursts),
// 2-stage cp.async pipeline, 1 CTA/SM (209KB smem), 288 CTAs.
// out += aH*(Lsym@R)_partial  (+ split 0: aL*(selfloop + bias))
// ---------------------------------------------------------------------------
__global__ void __launch_bounds__(256, 1) k_gemm(const float* __restrict__ L,
                                                 const float* __restrict__ bconv,
                                                 const float* __restrict__ paL,
                                                 const float* __restrict__ paH,
                                                 float* __restrict__ out) {
    extern __shared__ char smem[];
    const uint32_t sb = smem_u32(smem);
    const int tid  = threadIdx.x;
    const int lane = tid & 31;
    const int w    = tid >> 5;
    const int wm   = w >> 1;
    const int wn   = w & 1;
    const int g    = lane >> 2;
    const int t    = lane & 3;
    const int m0   = blockIdx.x * 128;
    const int cb   = blockIdx.y * CHPS;

    float acc[2][4][4];
#pragma unroll
    for (int mi = 0; mi < 2; ++mi)
#pragma unroll
        for (int ni = 0; ni < 4; ++ni)
#pragma unroll
            for (int q = 0; q < 4; ++q) acc[mi][ni][q] = 0.f;

    auto COPY = [&](int ct, int s) {
        uint32_t aB = sb + s * STAGE_B;
        uint32_t bB = aB + A_STAGE_B;
        const float* Ap = L + (size_t)m0 * NN + (size_t)(cb + ct) * 128;
#pragma unroll
        for (int i = 0; i < 16; ++i) {
            int idx = tid + i * 256;
            int row = idx >> 5, c16 = idx & 31;
            cp16(aB + row * (A_ROW_F * 4) + c16 * 16, Ap + (size_t)row * NN + c16 * 4);
        }
        const float* Bp = g_R + (size_t)(cb + ct) * 128 * 64;
#pragma unroll
        for (int i = 0; i < 8; ++i) {
            int idx = tid + i * 256;
            int k = idx >> 4, c = idx & 15;
            cp16(bB + k * (B_ROW_F * 4) + c * 16, Bp + (size_t)k * 64 + c * 4);
        }
    };

    COPY(0, 0); CP_COMMIT();
    COPY(1, 1); CP_COMMIT();

    for (int ct = 0; ct < CHPS; ++ct) {
        CP_WAIT1();
        __syncthreads();

        const float* sA = (const float*)(smem + (ct & 1) * STAGE_B);
        const float* sB = (const float*)(smem + (ct & 1) * STAGE_B + A_STAGE_B);

#pragma unroll 4
        for (int ks = 0; ks < 16; ++ks) {
            uint32_t a[2][4], b[4][2];
            int kc = ks * 8 + t;
#pragma unroll
            for (int mi = 0; mi < 2; ++mi) {
                int r = wm * 32 + mi * 16 + g;
                a[mi][0] = f2tf32(sA[r * A_ROW_F + kc]);
                a[mi][1] = f2tf32(sA[(r + 8) * A_ROW_F + kc]);
                a[mi][2] = f2tf32(sA[r * A_ROW_F + kc + 4]);
                a[mi][3] = f2tf32(sA[(r + 8) * A_ROW_F + kc + 4]);
            }
#pragma unroll
            for (int ni = 0; ni < 4; ++ni) {
                int n = wn * 32 + ni * 8 + g;
                b[ni][0] = __float_as_uint(sB[kc * B_ROW_F + n]);
                b[ni][1] = __float_as_uint(sB[(kc + 4) * B_ROW_F + n]);
            }
#pragma unroll
            for (int mi = 0; mi < 2; ++mi)
#pragma unroll
                for (int ni = 0; ni < 4; ++ni)
                    mma_tf32(acc[mi][ni], a[mi], b[ni]);
        }

        __syncthreads();
        if (ct + 2 < CHPS) COPY(ct + 2, ct & 1);
        CP_COMMIT();
    }

    // epilogue: red.v2 accumulate; split 0 adds exact self-loop + bias
    const float aLv = *paL, aHv = *paH;
    const bool  z0  = (blockIdx.y == 0);
#pragma unroll
    for (int mi = 0; mi < 2; ++mi) {
#pragma unroll
        for (int half = 0; half < 2; ++half) {
            int row = m0 + wm * 32 + mi * 16 + half * 8 + g;
            float di = g_dinv[row];
            float d2 = di * di;
            size_t rb = (size_t)row * 64;
#pragma unroll
            for (int ni = 0; ni < 4; ++ni) {
                int c = wn * 32 + ni * 8 + t * 2;
                float vx = aHv * acc[mi][ni][half * 2 + 0];
                float vy = aHv * acc[mi][ni][half * 2 + 1];
                if (z0) {
                    float2 xw = *(const float2*)&g_XW[rb + c];
                    float2 bb = *(const float2*)&bconv[c];
                    vx += aLv * (d2 * xw.x + bb.x);
                    vy += aLv * (d2 * xw.y + bb.y);
                }
                red2(&out[rb + c], vx, vy);
            }
        }
    }
}

// ---------------------------------------------------------------------------
extern "C" void kernel_launch(void* const* d_in, const int* in_sizes, int n_in,
                              void* d_out, int out_size) {
    const float* x  = (const float*)d_in[0];
    const int*   ei = (const int*)d_in[1];
    const float* Ls = (const float*)d_in[2];
    const float* Wh = (const float*)d_in[3];
    const float* Wc = (const float*)d_in[4];
    const float* bc = (const float*)d_in[5];
    const float* aL = (const float*)d_in[6];
    const float* aH = (const float*)d_in[7];
    float* out = (float*)d_out;

    cudaFuncSetAttribute(k_xw,   cudaFuncAttributeMaxDynamicSharedMemorySize, SM_XW);
    cudaFuncSetAttribute(k_gemm, cudaFuncAttributeMaxDynamicSharedMemorySize, SM_GEMM);

    k_init<<<(NN * DD) / 256, 256>>>(out);
    k_deg<<<(EE + 255) / 256, 256>>>(ei);
    k_dinv<<<(NN + 255) / 256, 256>>>();
    k_xw<<<96, 256, SM_XW>>>(x, Wh, Wc);
    k_scatter<<<(EE * 16) / 256, 256>>>(ei, aL, out);
    k_gemm<<<dim3(96, KSPLIT), 256, SM_GEMM>>>(Ls, bc, aL, aH, out);
}

// round 7
// speedup vs baseline: 3.2140x; 1.0308x over previous
#include <cuda_runtime.h>
#include <cuda_fp16.h>
#include <cstdint>

#define NN 12288
#define EE 196608
#define DD 64
#define KSPLIT 3
#define CHPS 32                   // chunks of BK=128 per split (96 total / 3)
#define A_ROW_F 132               // fp32: 128 floats + 4 pad = 528 B
#define B_ROW_H 136               // fp16: 128 halves + 8 pad = 272 B
#define A_STAGE_B (128 * A_ROW_F * 4)   // 67584
#define B_STAGE_B (64 * B_ROW_H * 2)    // 17408
#define STAGE_B (A_STAGE_B + B_STAGE_B) // 84992
#define SM_GEMM (2 * STAGE_B)           // 169984
#define XW_ROW_F 68
#define SM_XW (2 * 128 * XW_ROW_F * 4)  // 69632

// scratch (device globals — no allocation allowed)
__device__ __half g_Rth[DD * NN]; // relu(x @ Wh^T)^T as fp16, [feat][node]
__device__ float  g_XW[NN * DD];  // x @ Wc^T (tf32 MMA), [node][64]
__device__ float  g_dinv[NN];
__device__ int    g_deg[NN];

// ---------------------------------------------------------------------------
__device__ __forceinline__ uint32_t smem_u32(const void* p) {
    uint32_t a;
    asm("{ .reg .u64 t; cvta.to.shared.u64 t, %1; cvt.u32.u64 %0, t; }"
        : "=r"(a) : "l"(p));
    return a;
}

__device__ __forceinline__ uint32_t f2tf32(float x) {
    uint32_t t;
    asm("cvt.rna.tf32.f32 %0, %1;" : "=r"(t) : "f"(x));
    return t;
}

__device__ __forceinline__ uint32_t pkh2(float lo, float hi) {
    __half2 h = __floats2half2_rn(lo, hi);   // h.x = lo, h.y = hi
    return *(uint32_t*)&h;
}

__device__ __forceinline__ void cp16(uint32_t dst, const void* src) {
    asm volatile("cp.async.cg.shared.global [%0], [%1], 16;"
                 :: "r"(dst), "l"(__cvta_generic_to_global(src)) : "memory");
}
#define CP_COMMIT() asm volatile("cp.async.commit_group;" ::: "memory")
#define CP_WAIT1()  asm volatile("cp.async.wait_group 1;"  ::: "memory")
#define CP_WAIT0()  asm volatile("cp.async.wait_group 0;"  ::: "memory")

__device__ __forceinline__ void mma_tf32(float* c, const uint32_t* a, const uint32_t* b) {
    asm volatile(
        "mma.sync.aligned.m16n8k8.row.col.f32.tf32.tf32.f32 "
        "{%0,%1,%2,%3}, {%4,%5,%6,%7}, {%8,%9}, {%0,%1,%2,%3};"
        : "+f"(c[0]), "+f"(c[1]), "+f"(c[2]), "+f"(c[3])
        : "r"(a[0]), "r"(a[1]), "r"(a[2]), "r"(a[3]), "r"(b[0]), "r"(b[1]));
}

__device__ __forceinline__ void mma_f16(float* c, const uint32_t* a, const uint32_t* b) {
    asm volatile(
        "mma.sync.aligned.m16n8k16.row.col.f32.f16.f16.f32 "
        "{%0,%1,%2,%3}, {%4,%5,%6,%7}, {%8,%9}, {%0,%1,%2,%3};"
        : "+f"(c[0]), "+f"(c[1]), "+f"(c[2]), "+f"(c[3])
        : "r"(a[0]), "r"(a[1]), "r"(a[2]), "r"(a[3]), "r"(b[0]), "r"(b[1]));
}

__device__ __forceinline__ void red2(float* p, float x, float y) {
    asm volatile("red.global.add.v2.f32 [%0], {%1,%2};"
                 :: "l"(__cvta_generic_to_global(p)), "f"(x), "f"(y) : "memory");
}
__device__ __forceinline__ void red4(float* p, float x, float y, float z, float w) {
    asm volatile("red.global.add.v4.f32 [%0], {%1,%2,%3,%4};"
                 :: "l"(__cvta_generic_to_global(p)), "f"(x), "f"(y), "f"(z), "f"(w)
                 : "memory");
}

// ---------------------------------------------------------------------------
__global__ void k_init(float* __restrict__ out) {
    int i = blockIdx.x * 256 + threadIdx.x;   // grid = NN*DD/256
    out[i] = 0.0f;
    if (i < NN) g_deg[i] = 1;
}

__global__ void k_deg(const int* __restrict__ ei) {
    int e = blockIdx.x * 256 + threadIdx.x;
    if (e < EE) atomicAdd(&g_deg[ei[EE + e]], 1);
}

__global__ void k_dinv() {
    int i = blockIdx.x * 256 + threadIdx.x;
    if (i < NN) g_dinv[i] = rsqrtf((float)g_deg[i]);
}

// ---------------------------------------------------------------------------
// Fused projections via tensor cores: [R | XW] = x @ [Wh ; Wc]^T
// R written as fp16 TRANSPOSED [64][NN] (SMEM bounce), XW as fp32 [NN][64].
// ---------------------------------------------------------------------------
__global__ void __launch_bounds__(256) k_xw(const float* __restrict__ x,
                                            const float* __restrict__ Wh,
                                            const float* __restrict__ Wc) {
    extern __shared__ char smem[];
    const uint32_t sb = smem_u32(smem);
    const float* sX = (const float*)smem;
    const float* sW = (const float*)(smem + 128 * XW_ROW_F * 4);
    const uint32_t sWb = sb + 128 * XW_ROW_F * 4;

    const int tid  = threadIdx.x;
    const int lane = tid & 31;
    const int w    = tid >> 5;
    const int wm   = w >> 1;
    const int wn   = w & 1;
    const int g    = lane >> 2;
    const int t    = lane & 3;
    const int m0   = blockIdx.x * 128;

#pragma unroll
    for (int i = 0; i < 8; ++i) {
        int idx = tid + i * 256;
        int r = idx >> 4, c = idx & 15;
        cp16(sb + r * (XW_ROW_F * 4) + c * 16, x + (size_t)(m0 + r) * 64 + c * 4);
        const float* wsrc = (r < 64) ? (Wh + (size_t)r * 64 + c * 4)
                                     : (Wc + (size_t)(r - 64) * 64 + c * 4);
        cp16(sWb + r * (XW_ROW_F * 4) + c * 16, wsrc);
    }
    CP_COMMIT();
    CP_WAIT0();
    __syncthreads();

    float acc[2][8][4];
#pragma unroll
    for (int mi = 0; mi < 2; ++mi)
#pragma unroll
        for (int ni = 0; ni < 8; ++ni)
#pragma unroll
            for (int q = 0; q < 4; ++q) acc[mi][ni][q] = 0.f;

#pragma unroll
    for (int ks = 0; ks < 8; ++ks) {
        int kc = ks * 8 + t;
        uint32_t a[2][4], b[8][2];
#pragma unroll
        for (int mi = 0; mi < 2; ++mi) {
            int r = wm * 32 + mi * 16 + g;
            a[mi][0] = f2tf32(sX[r * XW_ROW_F + kc]);
            a[mi][1] = f2tf32(sX[(r + 8) * XW_ROW_F + kc]);
            a[mi][2] = f2tf32(sX[r * XW_ROW_F + kc + 4]);
            a[mi][3] = f2tf32(sX[(r + 8) * XW_ROW_F + kc + 4]);
        }
#pragma unroll
        for (int ni = 0; ni < 8; ++ni) {
            int n = wn * 64 + ni * 8 + g;
            b[ni][0] = f2tf32(sW[n * XW_ROW_F + kc]);
            b[ni][1] = f2tf32(sW[n * XW_ROW_F + kc + 4]);
        }
#pragma unroll
        for (int mi = 0; mi < 2; ++mi)
#pragma unroll
            for (int ni = 0; ni < 8; ++ni)
                mma_tf32(acc[mi][ni], a[mi], b[ni]);
    }

    __syncthreads();   // done reading sX/sW; reuse smem as fp16 transpose tile
    __half* sT = (__half*)smem;   // [64 cols][B_ROW_H=136 rows-pitch] fp16

#pragma unroll
    for (int mi = 0; mi < 2; ++mi) {
#pragma unroll
        for (int half = 0; half < 2; ++half) {
            int rloc = wm * 32 + mi * 16 + half * 8 + g;   // 0..127
            size_t rb = (size_t)(m0 + rloc) * 64;
#pragma unroll
            for (int ni = 0; ni < 8; ++ni) {
                int c = ni * 8 + t * 2;
                float v0 = acc[mi][ni][half * 2 + 0];
                float v1 = acc[mi][ni][half * 2 + 1];
                if (wn == 0) {   // R branch: relu + fp16, transpose in SMEM
                    sT[(c + 0) * B_ROW_H + rloc] = __float2half_rn(fmaxf(v0, 0.f));
                    sT[(c + 1) * B_ROW_H + rloc] = __float2half_rn(fmaxf(v1, 0.f));
                } else {         // XW branch: exact-ish fp32
                    float2 o; o.x = v0; o.y = v1;
                    *(float2*)&g_XW[rb + c] = o;
                }
            }
        }
    }
    __syncthreads();

    // coalesced store of the transposed fp16 R tile: 64 rows x 256B
#pragma unroll
    for (int i = 0; i < 4; ++i) {
        int idx = tid + i * 256;        // 0..1023 16B slots
        int c = idx >> 4, j = idx & 15;
        uint4 v = *(const uint4*)&sT[c * B_ROW_H + j * 8];
        *(uint4*)&g_Rth[(size_t)c * NN + m0 + j * 8] = v;
    }
}

// ---------------------------------------------------------------------------
// edge scatter straight into out: out[col] += aL * dinv[r]*dinv[c] * XW[row]
// ---------------------------------------------------------------------------
__global__ void __launch_bounds__(256) k_scatter(const int* __restrict__ ei,
                                                 const float* __restrict__ paL,
                                                 float* __restrict__ out) {
    int tt = blockIdx.x * 256 + threadIdx.x;   // grid = EE*16/256
    int e = tt >> 4;
    int q = tt & 15;
    int r = ei[e];
    int c = ei[EE + e];
    float norm = (*paL) * g_dinv[r] * g_dinv[c];
    float4 v = ((const float4*)g_XW)[r * 16 + q];
    red4(&out[c * 64 + q * 4], norm * v.x, norm * v.y, norm * v.z, norm * v.w);
}

// ---------------------------------------------------------------------------
// Main GEMM via mma.sync fp16 m16n8k16 (fp32 accum), split-K=3, BK=128,
// 2-stage cp.async. A fp32 in SMEM (cvt to fp16 at fragment load), B fp16.
// out += aH*(Lsym@R)_partial  (+ split 0: aL*(selfloop + bias))
// ---------------------------------------------------------------------------
__global__ void __launch_bounds__(256, 1) k_gemm(const float* __restrict__ L,
                                                 const float* __restrict__ bconv,
                                                 const float* __restrict__ paL,
                                                 const float* __restrict__ paH,
                                                 float* __restrict__ out) {
    extern __shared__ char smem[];
    const uint32_t sb = smem_u32(smem);
    const int tid  = threadIdx.x;
    const int lane = tid & 31;
    const int w    = tid >> 5;
    const int wm   = w >> 1;
    const int wn   = w & 1;
    const int g    = lane >> 2;
    const int t    = lane & 3;
    const int m0   = blockIdx.x * 128;
    const int cb   = blockIdx.y * CHPS;

    float acc[2][4][4];
#pragma unroll
    for (int mi = 0; mi < 2; ++mi)
#pragma unroll
        for (int ni = 0; ni < 4; ++ni)
#pragma unroll
            for (int q = 0; q < 4; ++q) acc[mi][ni][q] = 0.f;

    auto COPY = [&](int ct, int s) {
        uint32_t aB = sb + s * STAGE_B;
        uint32_t bB = aB + A_STAGE_B;
        const float* Ap = L + (size_t)m0 * NN + (size_t)(cb + ct) * 128;
#pragma unroll
        for (int i = 0; i < 16; ++i) {
            int idx = tid + i * 256;
            int row = idx >> 5, c16 = idx & 31;
            cp16(aB + row * (A_ROW_F * 4) + c16 * 16, Ap + (size_t)row * NN + c16 * 4);
        }
        const __half* Bp = g_Rth + (size_t)(cb + ct) * 128;
#pragma unroll
        for (int i = 0; i < 4; ++i) {
            int idx = tid + i * 256;        // 0..1023: 64 rows x 16 chunks
            int n = idx >> 4, c = idx & 15;
            cp16(bB + n * (B_ROW_H * 2) + c * 16, Bp + (size_t)n * NN + c * 8);
        }
    };

    COPY(0, 0); CP_COMMIT();
    COPY(1, 1); CP_COMMIT();

    for (int ct = 0; ct < CHPS; ++ct) {
        CP_WAIT1();
        __syncthreads();

        const float*  sA = (const float*)(smem + (ct & 1) * STAGE_B);
        const __half* sB = (const __half*)(smem + (ct & 1) * STAGE_B + A_STAGE_B);

#pragma unroll 4
        for (int ks = 0; ks < 8; ++ks) {
            uint32_t a[2][4], b[4][2];
            int kb = ks * 16;
#pragma unroll
            for (int mi = 0; mi < 2; ++mi) {
                int r = wm * 32 + mi * 16 + g;
                float2 p0 = *(const float2*)&sA[r * A_ROW_F + kb + 2 * t];
                float2 p1 = *(const float2*)&sA[(r + 8) * A_ROW_F + kb + 2 * t];
                float2 p2 = *(const float2*)&sA[r * A_ROW_F + kb + 8 + 2 * t];
                float2 p3 = *(const float2*)&sA[(r + 8) * A_ROW_F + kb + 8 + 2 * t];
                a[mi][0] = pkh2(p0.x, p0.y);
                a[mi][1] = pkh2(p1.x, p1.y);
                a[mi][2] = pkh2(p2.x, p2.y);
                a[mi][3] = pkh2(p3.x, p3.y);
            }
#pragma unroll
            for (int ni = 0; ni < 4; ++ni) {
                int n = wn * 32 + ni * 8 + g;
                b[ni][0] = *(const uint32_t*)&sB[n * B_ROW_H + kb + 2 * t];
                b[ni][1] = *(const uint32_t*)&sB[n * B_ROW_H + kb + 8 + 2 * t];
            }
#pragma unroll
            for (int mi = 0; mi < 2; ++mi)
#pragma unroll
                for (int ni = 0; ni < 4; ++ni)
                    mma_f16(acc[mi][ni], a[mi], b[ni]);
        }

        __syncthreads();
        if (ct + 2 < CHPS) COPY(ct + 2, ct & 1);
        CP_COMMIT();
    }

    // epilogue: red.v2 accumulate; split 0 adds exact self-loop + bias
    const float aLv = *paL, aHv = *paH;
    const bool  z0  = (blockIdx.y == 0);
#pragma unroll
    for (int mi = 0; mi < 2; ++mi) {
#pragma unroll
        for (int half = 0; half < 2; ++half) {
            int row = m0 + wm * 32 + mi * 16 + half * 8 + g;
            float di = g_dinv[row];
            float d2 = di * di;
            size_t rb = (size_t)row * 64;
#pragma unroll
            for (int ni = 0; ni < 4; ++ni) {
                int c = wn * 32 + ni * 8 + t * 2;
                float vx = aHv * acc[mi][ni][half * 2 + 0];
                float vy = aHv * acc[mi][ni][half * 2 + 1];
                if (z0) {
                    float2 xw = *(const float2*)&g_XW[rb + c];
                    float2 bb = *(const float2*)&bconv[c];
                    vx += aLv * (d2 * xw.x + bb.x);
                    vy += aLv * (d2 * xw.y + bb.y);
                }
                red2(&out[rb + c], vx, vy);
            }
        }
    }
}

// ---------------------------------------------------------------------------
extern "C" void kernel_launch(void* const* d_in, const int* in_sizes, int n_in,
                              void* d_out, int out_size) {
    const float* x  = (const float*)d_in[0];
    const int*   ei = (const int*)d_in[1];
    const float* Ls = (const float*)d_in[2];
    const float* Wh = (const float*)d_in[3];
    const float* Wc = (const float*)d_in[4];
    const float* bc = (const float*)d_in[5];
    const float* aL = (const float*)d_in[6];
    const float* aH = (const float*)d_in[7];
    float* out = (float*)d_out;

    cudaFuncSetAttribute(k_xw,   cudaFuncAttributeMaxDynamicSharedMemorySize, SM_XW);
    cudaFuncSetAttribute(k_gemm, cudaFuncAttributeMaxDynamicSharedMemorySize, SM_GEMM);

    k_init<<<(NN * DD) / 256, 256>>>(out);
    k_deg<<<(EE + 255) / 256, 256>>>(ei);
    k_dinv<<<(NN + 255) / 256, 256>>>();
    k_xw<<<96, 256, SM_XW>>>(x, Wh, Wc);
    k_scatter<<<(EE * 16) / 256, 256>>>(ei, aL, out);
    k_gemm<<<dim3(96, KSPLIT), 256, SM_GEMM>>>(Ls, bc, aL, aH, out);
}

// round 8
// speedup vs baseline: 3.2877x; 1.0229x over previous
#include <cuda_runtime.h>
#include <cuda_fp16.h>
#include <cstdint>

#define NN 12288
#define EE 196608
#define DD 64
#define KSPLIT 3
#define CHPS 64                   // chunks of BK=64 per split (192 total / 3)
#define NSTG 4
#define A_ROW_F 68                // fp32: 64 floats + 4 pad = 272 B
#define B_ROW_H 72                // fp16: 64 halves + 8 pad = 144 B
#define A_STAGE_B (128 * A_ROW_F * 4)   // 34816
#define B_STAGE_B (64 * B_ROW_H * 2)    // 9216
#define STAGE_B (A_STAGE_B + B_STAGE_B) // 44032
#define SM_GEMM (NSTG * STAGE_B)        // 176128
#define XW_ROW_F 68
#define XW_T_PITCH 136
#define SM_XW (2 * 128 * XW_ROW_F * 4)  // 69632

// scratch (device globals — no allocation allowed)
__device__ __half g_Rth[DD * NN]; // relu(x @ Wh^T)^T as fp16, [feat][node]
__device__ float  g_XW[NN * DD];  // x @ Wc^T (tf32 MMA), [node][64]
__device__ int    g_deg[NN];

// ---------------------------------------------------------------------------
__device__ __forceinline__ uint32_t smem_u32(const void* p) {
    uint32_t a;
    asm("{ .reg .u64 t; cvta.to.shared.u64 t, %1; cvt.u32.u64 %0, t; }"
        : "=r"(a) : "l"(p));
    return a;
}

__device__ __forceinline__ uint32_t f2tf32(float x) {
    uint32_t t;
    asm("cvt.rna.tf32.f32 %0, %1;" : "=r"(t) : "f"(x));
    return t;
}

__device__ __forceinline__ uint32_t pkh2(float lo, float hi) {
    __half2 h = __floats2half2_rn(lo, hi);
    return *(uint32_t*)&h;
}

__device__ __forceinline__ void cp16(uint32_t dst, const void* src) {
    asm volatile("cp.async.cg.shared.global [%0], [%1], 16;"
                 :: "r"(dst), "l"(__cvta_generic_to_global(src)) : "memory");
}
#define CP_COMMIT() asm volatile("cp.async.commit_group;" ::: "memory")
#define CP_WAIT2()  asm volatile("cp.async.wait_group 2;"  ::: "memory")
#define CP_WAIT0()  asm volatile("cp.async.wait_group 0;"  ::: "memory")

__device__ __forceinline__ void mma_tf32(float* c, const uint32_t* a, const uint32_t* b) {
    asm volatile(
        "mma.sync.aligned.m16n8k8.row.col.f32.tf32.tf32.f32 "
        "{%0,%1,%2,%3}, {%4,%5,%6,%7}, {%8,%9}, {%0,%1,%2,%3};"
        : "+f"(c[0]), "+f"(c[1]), "+f"(c[2]), "+f"(c[3])
        : "r"(a[0]), "r"(a[1]), "r"(a[2]), "r"(a[3]), "r"(b[0]), "r"(b[1]));
}

__device__ __forceinline__ void mma_f16(float* c, const uint32_t* a, const uint32_t* b) {
    asm volatile(
        "mma.sync.aligned.m16n8k16.row.col.f32.f16.f16.f32 "
        "{%0,%1,%2,%3}, {%4,%5,%6,%7}, {%8,%9}, {%0,%1,%2,%3};"
        : "+f"(c[0]), "+f"(c[1]), "+f"(c[2]), "+f"(c[3])
        : "r"(a[0]), "r"(a[1]), "r"(a[2]), "r"(a[3]), "r"(b[0]), "r"(b[1]));
}

__device__ __forceinline__ void red2(float* p, float x, float y) {
    asm volatile("red.global.add.v2.f32 [%0], {%1,%2};"
                 :: "l"(__cvta_generic_to_global(p)), "f"(x), "f"(y) : "memory");
}
__device__ __forceinline__ void red4(float* p, float x, float y, float z, float w) {
    asm volatile("red.global.add.v4.f32 [%0], {%1,%2,%3,%4};"
                 :: "l"(__cvta_generic_to_global(p)), "f"(x), "f"(y), "f"(z), "f"(w)
                 : "memory");
}

// ---------------------------------------------------------------------------
__global__ void k_init(float* __restrict__ out) {
    int i = blockIdx.x * 256 + threadIdx.x;   // grid = NN*DD/256
    out[i] = 0.0f;
    if (i < NN) g_deg[i] = 1;
}

__global__ void k_deg(const int* __restrict__ ei) {
    int e = blockIdx.x * 256 + threadIdx.x;
    if (e < EE) atomicAdd(&g_deg[ei[EE + e]], 1);
}

// ---------------------------------------------------------------------------
// Fused projections via tensor cores: [R | XW] = x @ [Wh ; Wc]^T
// R written as fp16 TRANSPOSED [64][NN] (SMEM bounce), XW as fp32 [NN][64].
// ---------------------------------------------------------------------------
__global__ void __launch_bounds__(256) k_xw(const float* __restrict__ x,
                                            const float* __restrict__ Wh,
                                            const float* __restrict__ Wc) {
    extern __shared__ char smem[];
    const uint32_t sb = smem_u32(smem);
    const float* sX = (const float*)smem;
    const float* sW = (const float*)(smem + 128 * XW_ROW_F * 4);
    const uint32_t sWb = sb + 128 * XW_ROW_F * 4;

    const int tid  = threadIdx.x;
    const int lane = tid & 31;
    const int w    = tid >> 5;
    const int wm   = w >> 1;
    const int wn   = w & 1;
    const int g    = lane >> 2;
    const int t    = lane & 3;
    const int m0   = blockIdx.x * 128;

#pragma unroll
    for (int i = 0; i < 8; ++i) {
        int idx = tid + i * 256;
        int r = idx >> 4, c = idx & 15;
        cp16(sb + r * (XW_ROW_F * 4) + c * 16, x + (size_t)(m0 + r) * 64 + c * 4);
        const float* wsrc = (r < 64) ? (Wh + (size_t)r * 64 + c * 4)
                                     : (Wc + (size_t)(r - 64) * 64 + c * 4);
        cp16(sWb + r * (XW_ROW_F * 4) + c * 16, wsrc);
    }
    CP_COMMIT();
    CP_WAIT0();
    __syncthreads();

    float acc[2][8][4];
#pragma unroll
    for (int mi = 0; mi < 2; ++mi)
#pragma unroll
        for (int ni = 0; ni < 8; ++ni)
#pragma unroll
            for (int q = 0; q < 4; ++q) acc[mi][ni][q] = 0.f;

#pragma unroll
    for (int ks = 0; ks < 8; ++ks) {
        int kc = ks * 8 + t;
        uint32_t a[2][4], b[8][2];
#pragma unroll
        for (int mi = 0; mi < 2; ++mi) {
            int r = wm * 32 + mi * 16 + g;
            a[mi][0] = f2tf32(sX[r * XW_ROW_F + kc]);
            a[mi][1] = f2tf32(sX[(r + 8) * XW_ROW_F + kc]);
            a[mi][2] = f2tf32(sX[r * XW_ROW_F + kc + 4]);
            a[mi][3] = f2tf32(sX[(r + 8) * XW_ROW_F + kc + 4]);
        }
#pragma unroll
        for (int ni = 0; ni < 8; ++ni) {
            int n = wn * 64 + ni * 8 + g;
            b[ni][0] = f2tf32(sW[n * XW_ROW_F + kc]);
            b[ni][1] = f2tf32(sW[n * XW_ROW_F + kc + 4]);
        }
#pragma unroll
        for (int mi = 0; mi < 2; ++mi)
#pragma unroll
            for (int ni = 0; ni < 8; ++ni)
                mma_tf32(acc[mi][ni], a[mi], b[ni]);
    }

    __syncthreads();   // reuse smem as fp16 transpose tile
    __half* sT = (__half*)smem;   // [64 cols][XW_T_PITCH] fp16

#pragma unroll
    for (int mi = 0; mi < 2; ++mi) {
#pragma unroll
        for (int half = 0; half < 2; ++half) {
            int rloc = wm * 32 + mi * 16 + half * 8 + g;   // 0..127
            size_t rb = (size_t)(m0 + rloc) * 64;
#pragma unroll
            for (int ni = 0; ni < 8; ++ni) {
                int c = ni * 8 + t * 2;
                float v0 = acc[mi][ni][half * 2 + 0];
                float v1 = acc[mi][ni][half * 2 + 1];
                if (wn == 0) {
                    sT[(c + 0) * XW_T_PITCH + rloc] = __float2half_rn(fmaxf(v0, 0.f));
                    sT[(c + 1) * XW_T_PITCH + rloc] = __float2half_rn(fmaxf(v1, 0.f));
                } else {
                    float2 o; o.x = v0; o.y = v1;
                    *(float2*)&g_XW[rb + c] = o;
                }
            }
        }
    }
    __syncthreads();

#pragma unroll
    for (int i = 0; i < 4; ++i) {
        int idx = tid + i * 256;        // 0..1023 16B slots
        int c = idx >> 4, j = idx & 15;
        uint4 v = *(const uint4*)&sT[c * XW_T_PITCH + j * 8];
        *(uint4*)&g_Rth[(size_t)c * NN + m0 + j * 8] = v;
    }
}

// ---------------------------------------------------------------------------
// edge scatter straight into out: out[col] += aL * dinv[r]*dinv[c] * XW[row]
// (dinv computed on the fly from g_deg)
// ---------------------------------------------------------------------------
__global__ void __launch_bounds__(256) k_scatter(const int* __restrict__ ei,
                                                 const float* __restrict__ paL,
                                                 float* __restrict__ out) {
    int tt = blockIdx.x * 256 + threadIdx.x;   // grid = EE*16/256
    int e = tt >> 4;
    int q = tt & 15;
    int r = ei[e];
    int c = ei[EE + e];
    float norm = (*paL) * rsqrtf((float)g_deg[r]) * rsqrtf((float)g_deg[c]);
    float4 v = ((const float4*)g_XW)[r * 16 + q];
    red4(&out[c * 64 + q * 4], norm * v.x, norm * v.y, norm * v.z, norm * v.w);
}

// ---------------------------------------------------------------------------
// Main GEMM via mma.sync fp16 m16n8k16 (fp32 accum), split-K=3, BK=64,
// 4-stage cp.async pipeline (copies issued 3 chunks ahead, ~120KB in flight).
// out += aH*(Lsym@R)_partial  (+ split 0: aL*(selfloop + bias))
// ---------------------------------------------------------------------------
__global__ void __launch_bounds__(256, 1) k_gemm(const float* __restrict__ L,
                                                 const float* __restrict__ bconv,
                                                 const float* __restrict__ paL,
                                                 const float* __restrict__ paH,
                                                 float* __restrict__ out) {
    extern __shared__ char smem[];
    const uint32_t sb = smem_u32(smem);
    const int tid  = threadIdx.x;
    const int lane = tid & 31;
    const int w    = tid >> 5;
    const int wm   = w >> 1;
    const int wn   = w & 1;
    const int g    = lane >> 2;
    const int t    = lane & 3;
    const int m0   = blockIdx.x * 128;
    const int cb   = blockIdx.y * CHPS;

    float acc[2][4][4];
#pragma unroll
    for (int mi = 0; mi < 2; ++mi)
#pragma unroll
        for (int ni = 0; ni < 4; ++ni)
#pragma unroll
            for (int q = 0; q < 4; ++q) acc[mi][ni][q] = 0.f;

    auto COPY = [&](int ct) {
        int s = ct & (NSTG - 1);
        uint32_t aB = sb + s * STAGE_B;
        uint32_t bB = aB + A_STAGE_B;
        const float* Ap = L + (size_t)m0 * NN + (size_t)(cb + ct) * 64;
#pragma unroll
        for (int i = 0; i < 8; ++i) {
            int idx = tid + i * 256;
            int row = idx >> 4, c16 = idx & 15;
            cp16(aB + row * (A_ROW_F * 4) + c16 * 16, Ap + (size_t)row * NN + c16 * 4);
        }
        const __half* Bp = g_Rth + (size_t)(cb + ct) * 64;
#pragma unroll
        for (int i = 0; i < 2; ++i) {
            int idx = tid + i * 256;        // 0..511: 64 rows x 8 chunks
            int n = idx >> 3, c = idx & 7;
            cp16(bB + n * (B_ROW_H * 2) + c * 16, Bp + (size_t)n * NN + c * 8);
        }
    };

    COPY(0); CP_COMMIT();
    COPY(1); CP_COMMIT();
    COPY(2); CP_COMMIT();

    for (int ct = 0; ct < CHPS; ++ct) {
        CP_WAIT2();          // chunk ct resident (<=2 pending: ct+1, ct+2)
        __syncthreads();     // all threads done with chunk ct-1 -> its stage free
        if (ct + 3 < CHPS) COPY(ct + 3);
        CP_COMMIT();

        const float*  sA = (const float*)(smem + (ct & (NSTG - 1)) * STAGE_B);
        const __half* sB = (const __half*)(smem + (ct & (NSTG - 1)) * STAGE_B + A_STAGE_B);

#pragma unroll
        for (int ks = 0; ks < 4; ++ks) {
            uint32_t a[2][4], b[4][2];
            int kb = ks * 16;
#pragma unroll
            for (int mi = 0; mi < 2; ++mi) {
                int r = wm * 32 + mi * 16 + g;
                float2 p0 = *(const float2*)&sA[r * A_ROW_F + kb + 2 * t];
                float2 p1 = *(const float2*)&sA[(r + 8) * A_ROW_F + kb + 2 * t];
                float2 p2 = *(const float2*)&sA[r * A_ROW_F + kb + 8 + 2 * t];
                float2 p3 = *(const float2*)&sA[(r + 8) * A_ROW_F + kb + 8 + 2 * t];
                a[mi][0] = pkh2(p0.x, p0.y);
                a[mi][1] = pkh2(p1.x, p1.y);
                a[mi][2] = pkh2(p2.x, p2.y);
                a[mi][3] = pkh2(p3.x, p3.y);
            }
#pragma unroll
            for (int ni = 0; ni < 4; ++ni) {
                int n = wn * 32 + ni * 8 + g;
                b[ni][0] = *(const uint32_t*)&sB[n * B_ROW_H + kb + 2 * t];
                b[ni][1] = *(const uint32_t*)&sB[n * B_ROW_H + kb + 8 + 2 * t];
            }
#pragma unroll
            for (int mi = 0; mi < 2; ++mi)
#pragma unroll
                for (int ni = 0; ni < 4; ++ni)
                    mma_f16(acc[mi][ni], a[mi], b[ni]);
        }
    }

    // epilogue: red.v2 accumulate; split 0 adds exact self-loop + bias
    const float aLv = *paL, aHv = *paH;
    const bool  z0  = (blockIdx.y == 0);
#pragma unroll
    for (int mi = 0; mi < 2; ++mi) {
#pragma unroll
        for (int half = 0; half < 2; ++half) {
            int row = m0 + wm * 32 + mi * 16 + half * 8 + g;
            float d2 = 1.0f / (float)g_deg[row];
            size_t rb = (size_t)row * 64;
#pragma unroll
            for (int ni = 0; ni < 4; ++ni) {
                int c = wn * 32 + ni * 8 + t * 2;
                float vx = aHv * acc[mi][ni][half * 2 + 0];
                float vy = aHv * acc[mi][ni][half * 2 + 1];
                if (z0) {
                    float2 xw = *(const float2*)&g_XW[rb + c];
                    float2 bb = *(const float2*)&bconv[c];
                    vx += aLv * (d2 * xw.x + bb.x);
                    vy += aLv * (d2 * xw.y + bb.y);
                }
                red2(&out[rb + c], vx, vy);
            }
        }
    }
}

// ---------------------------------------------------------------------------
extern "C" void kernel_launch(void* const* d_in, const int* in_sizes, int n_in,
                              void* d_out, int out_size) {
    const float* x  = (const float*)d_in[0];
    const int*   ei = (const int*)d_in[1];
    const float* Ls = (const float*)d_in[2];
    const float* Wh = (const float*)d_in[3];
    const float* Wc = (const float*)d_in[4];
    const float* bc = (const float*)d_in[5];
    const float* aL = (const float*)d_in[6];
    const float* aH = (const float*)d_in[7];
    float* out = (float*)d_out;

    cudaFuncSetAttribute(k_xw,   cudaFuncAttributeMaxDynamicSharedMemorySize, SM_XW);
    cudaFuncSetAttribute(k_gemm, cudaFuncAttributeMaxDynamicSharedMemorySize, SM_GEMM);

    // order chosen so ncu (-s 5 -c 1) captures k_gemm
    k_init<<<(NN * DD) / 256, 256>>>(out);
    k_deg<<<(EE + 255) / 256, 256>>>(ei);
    k_xw<<<96, 256, SM_XW>>>(x, Wh, Wc);
    k_gemm<<<dim3(96, KSPLIT), 256, SM_GEMM>>>(Ls, bc, aL, aH, out);
    k_scatter<<<(EE * 16) / 256, 256>>>(ei, aL, out);
}

// round 10
// speedup vs baseline: 4.6642x; 1.4186x over previous
#include <cuda_runtime.h>
#include <cuda_fp16.h>
#include <cstdint>

#define NN 12288
#define EE 196608
#define DD 64
#define KSPLIT 3
#define CHPS 64                   // chunks of BK=64 per split (192 total / 3)
#define NSTG 3
#define ROW_H 72                  // fp16 row pitch: 64 halves + 8 pad = 144 B
#define A_STAGE_B (128 * ROW_H * 2)     // 18432
#define B_STAGE_B (64 * ROW_H * 2)      // 9216
#define STAGE_B (A_STAGE_B + B_STAGE_B) // 27648
#define SM_GEMM (NSTG * STAGE_B)        // 82944
#define XW_ROW_F 68
#define XW_T_PITCH 136
#define SM_XW (2 * 128 * XW_ROW_F * 4)  // 69632

// scratch (device globals — no allocation allowed)
__device__ __half g_Rth[DD * NN]; // relu(x @ Wh^T)^T as fp16, [feat][node]
__device__ float  g_XW[NN * DD];  // x @ Wc^T (tf32 MMA), [node][64]
__device__ int    g_deg[NN];

// ---------------------------------------------------------------------------
__device__ __forceinline__ uint32_t smem_u32(const void* p) {
    uint32_t a;
    asm("{ .reg .u64 t; cvta.to.shared.u64 t, %1; cvt.u32.u64 %0, t; }"
        : "=r"(a) : "l"(p));
    return a;
}

__device__ __forceinline__ uint32_t f2tf32(float x) {
    uint32_t t;
    asm("cvt.rna.tf32.f32 %0, %1;" : "=r"(t) : "f"(x));
    return t;
}

__device__ __forceinline__ uint32_t pkh2(float lo, float hi) {
    __half2 h = __floats2half2_rn(lo, hi);
    return *(uint32_t*)&h;
}

__device__ __forceinline__ void cp16(uint32_t dst, const void* src) {
    asm volatile("cp.async.cg.shared.global [%0], [%1], 16;"
                 :: "r"(dst), "l"(__cvta_generic_to_global(src)) : "memory");
}
#define CP_COMMIT() asm volatile("cp.async.commit_group;" ::: "memory")
#define CP_WAIT1()  asm volatile("cp.async.wait_group 1;"  ::: "memory")
#define CP_WAIT0()  asm volatile("cp.async.wait_group 0;"  ::: "memory")

__device__ __forceinline__ void mma_tf32(float* c, const uint32_t* a, const uint32_t* b) {
    asm volatile(
        "mma.sync.aligned.m16n8k8.row.col.f32.tf32.tf32.f32 "
        "{%0,%1,%2,%3}, {%4,%5,%6,%7}, {%8,%9}, {%0,%1,%2,%3};"
        : "+f"(c[0]), "+f"(c[1]), "+f"(c[2]), "+f"(c[3])
        : "r"(a[0]), "r"(a[1]), "r"(a[2]), "r"(a[3]), "r"(b[0]), "r"(b[1]));
}

__device__ __forceinline__ void mma_f16(float* c, const uint32_t* a, const uint32_t* b) {
    asm volatile(
        "mma.sync.aligned.m16n8k16.row.col.f32.f16.f16.f32 "
        "{%0,%1,%2,%3}, {%4,%5,%6,%7}, {%8,%9}, {%0,%1,%2,%3};"
        : "+f"(c[0]), "+f"(c[1]), "+f"(c[2]), "+f"(c[3])
        : "r"(a[0]), "r"(a[1]), "r"(a[2]), "r"(a[3]), "r"(b[0]), "r"(b[1]));
}

__device__ __forceinline__ void red2(float* p, float x, float y) {
    asm volatile("red.global.add.v2.f32 [%0], {%1,%2};"
                 :: "l"(__cvta_generic_to_global(p)), "f"(x), "f"(y) : "memory");
}
__device__ __forceinline__ void red4(float* p, float x, float y, float z, float w) {
    asm volatile("red.global.add.v4.f32 [%0], {%1,%2,%3,%4};"
                 :: "l"(__cvta_generic_to_global(p)), "f"(x), "f"(y), "f"(z), "f"(w)
                 : "memory");
}

// ---------------------------------------------------------------------------
__global__ void k_init(float* __restrict__ out) {
    int i = blockIdx.x * 256 + threadIdx.x;   // grid = NN*DD/256
    out[i] = 0.0f;
    if (i < NN) g_deg[i] = 1;
}

__global__ void k_deg(const int* __restrict__ ei) {
    int e = blockIdx.x * 256 + threadIdx.x;
    if (e < EE) atomicAdd(&g_deg[ei[EE + e]], 1);
}

// ---------------------------------------------------------------------------
// Fused projections via tensor cores: [R | XW] = x @ [Wh ; Wc]^T
// R written as fp16 TRANSPOSED [64][NN] (SMEM bounce), XW as fp32 [NN][64].
// ---------------------------------------------------------------------------
__global__ void __launch_bounds__(256) k_xw(const float* __restrict__ x,
                                            const float* __restrict__ Wh,
                                            const float* __restrict__ Wc) {
    extern __shared__ char smem[];
    const uint32_t sb = smem_u32(smem);
    const float* sX = (const float*)smem;
    const float* sW = (const float*)(smem + 128 * XW_ROW_F * 4);
    const uint32_t sWb = sb + 128 * XW_ROW_F * 4;

    const int tid  = threadIdx.x;
    const int lane = tid & 31;
    const int w    = tid >> 5;
    const int wm   = w >> 1;
    const int wn   = w & 1;
    const int g    = lane >> 2;
    const int t    = lane & 3;
    const int m0   = blockIdx.x * 128;

#pragma unroll
    for (int i = 0; i < 8; ++i) {
        int idx = tid + i * 256;
        int r = idx >> 4, c = idx & 15;
        cp16(sb + r * (XW_ROW_F * 4) + c * 16, x + (size_t)(m0 + r) * 64 + c * 4);
        const float* wsrc = (r < 64) ? (Wh + (size_t)r * 64 + c * 4)
                                     : (Wc + (size_t)(r - 64) * 64 + c * 4);
        cp16(sWb + r * (XW_ROW_F * 4) + c * 16, wsrc);
    }
    CP_COMMIT();
    CP_WAIT0();
    __syncthreads();

    float acc[2][8][4];
#pragma unroll
    for (int mi = 0; mi < 2; ++mi)
#pragma unroll
        for (int ni = 0; ni < 8; ++ni)
#pragma unroll
            for (int q = 0; q < 4; ++q) acc[mi][ni][q] = 0.f;

#pragma unroll
    for (int ks = 0; ks < 8; ++ks) {
        int kc = ks * 8 + t;
        uint32_t a[2][4], b[8][2];
#pragma unroll
        for (int mi = 0; mi < 2; ++mi) {
            int r = wm * 32 + mi * 16 + g;
            a[mi][0] = f2tf32(sX[r * XW_ROW_F + kc]);
            a[mi][1] = f2tf32(sX[(r + 8) * XW_ROW_F + kc]);
            a[mi][2] = f2tf32(sX[r * XW_ROW_F + kc + 4]);
            a[mi][3] = f2tf32(sX[(r + 8) * XW_ROW_F + kc + 4]);
        }
#pragma unroll
        for (int ni = 0; ni < 8; ++ni) {
            int n = wn * 64 + ni * 8 + g;
            b[ni][0] = f2tf32(sW[n * XW_ROW_F + kc]);
            b[ni][1] = f2tf32(sW[n * XW_ROW_F + kc + 4]);
        }
#pragma unroll
        for (int mi = 0; mi < 2; ++mi)
#pragma unroll
            for (int ni = 0; ni < 8; ++ni)
                mma_tf32(acc[mi][ni], a[mi], b[ni]);
    }

    __syncthreads();   // reuse smem as fp16 transpose tile
    __half* sT = (__half*)smem;   // [64 cols][XW_T_PITCH] fp16

#pragma unroll
    for (int mi = 0; mi < 2; ++mi) {
#pragma unroll
        for (int half = 0; half < 2; ++half) {
            int rloc = wm * 32 + mi * 16 + half * 8 + g;   // 0..127
            size_t rb = (size_t)(m0 + rloc) * 64;
#pragma unroll
            for (int ni = 0; ni < 8; ++ni) {
                int c = ni * 8 + t * 2;
                float v0 = acc[mi][ni][half * 2 + 0];
                float v1 = acc[mi][ni][half * 2 + 1];
                if (wn == 0) {
                    sT[(c + 0) * XW_T_PITCH + rloc] = __float2half_rn(fmaxf(v0, 0.f));
                    sT[(c + 1) * XW_T_PITCH + rloc] = __float2half_rn(fmaxf(v1, 0.f));
                } else {
                    float2 o; o.x = v0; o.y = v1;
                    *(float2*)&g_XW[rb + c] = o;
                }
            }
        }
    }
    __syncthreads();

#pragma unroll
    for (int i = 0; i < 4; ++i) {
        int idx = tid + i * 256;        // 0..1023 16B slots
        int c = idx >> 4, j = idx & 15;
        uint4 v = *(const uint4*)&sT[c * XW_T_PITCH + j * 8];
        *(uint4*)&g_Rth[(size_t)c * NN + m0 + j * 8] = v;
    }
}

// ---------------------------------------------------------------------------
// edge scatter straight into out: out[col] += aL * dinv[r]*dinv[c] * XW[row]
// ---------------------------------------------------------------------------
__global__ void __launch_bounds__(256) k_scatter(const int* __restrict__ ei,
                                                 const float* __restrict__ paL,
                                                 float* __restrict__ out) {
    int tt = blockIdx.x * 256 + threadIdx.x;   // grid = EE*16/256
    int e = tt >> 4;
    int q = tt & 15;
    int r = ei[e];
    int c = ei[EE + e];
    float norm = (*paL) * rsqrtf((float)g_deg[r]) * rsqrtf((float)g_deg[c]);
    float4 v = ((const float4*)g_XW)[r * 16 + q];
    red4(&out[c * 64 + q * 4], norm * v.x, norm * v.y, norm * v.z, norm * v.w);
}

// ---------------------------------------------------------------------------
// Main GEMM, fp16 m16n8k16 mma.sync, split-K=3, BK=64, 3-stage pipeline.
// A: LDG fp32 -> cvt fp16 -> STS; B: cp.async fp16. 2 CTAs/SM, 288 CTAs.
// Sync protocol per chunk: cp.async.wait_group -> __syncthreads -> issue
// next copies -> compute. The barrier AFTER the wait is what makes other
// threads' cp.async/STS data visible (R9's NaN was from omitting it).
// out += aH*(Lsym@R)_partial  (+ split 0: aL*(selfloop + bias))
// ---------------------------------------------------------------------------
__global__ void __launch_bounds__(256, 2) k_gemm(const float* __restrict__ L,
                                                 const float* __restrict__ bconv,
                                                 const float* __restrict__ paL,
                                                 const float* __restrict__ paH,
                                                 float* __restrict__ out) {
    extern __shared__ char smem[];
    const int tid  = threadIdx.x;
    const int lane = tid & 31;
    const int w    = tid >> 5;
    const int wm   = w >> 1;
    const int wn   = w & 1;
    const int g    = lane >> 2;
    const int t    = lane & 3;
    const int m0   = blockIdx.x * 128;
    const int cb   = blockIdx.y * CHPS;
    const uint32_t sb = smem_u32(smem);

    float acc[2][4][4];
#pragma unroll
    for (int mi = 0; mi < 2; ++mi)
#pragma unroll
        for (int ni = 0; ni < 4; ++ni)
#pragma unroll
            for (int q = 0; q < 4; ++q) acc[mi][ni][q] = 0.f;

    const int arow = tid >> 4;       // base row (8 rows x16 apart)
    const int ac4  = tid & 15;       // float4 col within 64

    float4 rA[8];                    // staged A chunk (fp32 from DRAM)

    auto LDGA = [&](int ct) {
        const float* Ap = L + (size_t)m0 * NN + (size_t)(cb + ct) * 64;
#pragma unroll
        for (int i = 0; i < 8; ++i)
            rA[i] = *(const float4*)(Ap + (size_t)(arow + i * 16) * NN + ac4 * 4);
    };
    auto STSA = [&](int ct) {
        char* aP = smem + (ct % NSTG) * STAGE_B;
#pragma unroll
        for (int i = 0; i < 8; ++i) {
            uint2 h;
            h.x = pkh2(rA[i].x, rA[i].y);
            h.y = pkh2(rA[i].z, rA[i].w);
            *(uint2*)(aP + (arow + i * 16) * (ROW_H * 2) + ac4 * 8) = h;
        }
    };
    auto CPB = [&](int ct) {
        uint32_t bB = sb + (ct % NSTG) * STAGE_B + A_STAGE_B;
        const __half* Bp = g_Rth + (size_t)(cb + ct) * 64;
#pragma unroll
        for (int i = 0; i < 2; ++i) {
            int idx = tid + i * 256;        // 0..511: 64 rows x 8 chunks
            int n = idx >> 3, c = idx & 7;
            cp16(bB + n * (ROW_H * 2) + c * 16, Bp + (size_t)n * NN + c * 8);
        }
    };

    // preamble: stages 0,1 filled; A regs staged for chunk 2
    LDGA(0); STSA(0);
    LDGA(1); STSA(1);
    CPB(0); CP_COMMIT();
    CPB(1); CP_COMMIT();
    LDGA(2);

    for (int ct = 0; ct < CHPS; ++ct) {
        CP_WAIT1();          // this thread's groups <= 1 pending: B(ct) issued-complete
        __syncthreads();     // publish ALL threads' cp.async B(ct) + STS A(ct);
                             // also proves stage (ct-1)%3 fully consumed -> free

        if (ct + 2 < CHPS) {
            STSA(ct + 2);    // into stage (ct+2)%3 == (ct-1)%3 (free)
            CPB(ct + 2);
            if (ct + 3 < CHPS) LDGA(ct + 3);
        }
        CP_COMMIT();         // unconditional: keeps group numbering aligned

        const __half* sA = (const __half*)(smem + (ct % NSTG) * STAGE_B);
        const __half* sB = (const __half*)(smem + (ct % NSTG) * STAGE_B + A_STAGE_B);

#pragma unroll
        for (int ks = 0; ks < 4; ++ks) {
            uint32_t a[2][4], b[4][2];
            int kb = ks * 16;
#pragma unroll
            for (int mi = 0; mi < 2; ++mi) {
                int r = wm * 32 + mi * 16 + g;
                a[mi][0] = *(const uint32_t*)&sA[r * ROW_H + kb + 2 * t];
                a[mi][1] = *(const uint32_t*)&sA[(r + 8) * ROW_H + kb + 2 * t];
                a[mi][2] = *(const uint32_t*)&sA[r * ROW_H + kb + 8 + 2 * t];
                a[mi][3] = *(const uint32_t*)&sA[(r + 8) * ROW_H + kb + 8 + 2 * t];
            }
#pragma unroll
            for (int ni = 0; ni < 4; ++ni) {
                int n = wn * 32 + ni * 8 + g;
                b[ni][0] = *(const uint32_t*)&sB[n * ROW_H + kb + 2 * t];
                b[ni][1] = *(const uint32_t*)&sB[n * ROW_H + kb + 8 + 2 * t];
            }
#pragma unroll
            for (int mi = 0; mi < 2; ++mi)
#pragma unroll
                for (int ni = 0; ni < 4; ++ni)
                    mma_f16(acc[mi][ni], a[mi], b[ni]);
        }
    }

    // epilogue: red.v2 accumulate; split 0 adds exact self-loop + bias
    const float aLv = *paL, aHv = *paH;
    const bool  z0  = (blockIdx.y == 0);
#pragma unroll
    for (int mi = 0; mi < 2; ++mi) {
#pragma unroll
        for (int half = 0; half < 2; ++half) {
            int row = m0 + wm * 32 + mi * 16 + half * 8 + g;
            float d2 = 1.0f / (float)g_deg[row];
            size_t rb = (size_t)row * 64;
#pragma unroll
            for (int ni = 0; ni < 4; ++ni) {
                int c = wn * 32 + ni * 8 + t * 2;
                float vx = aHv * acc[mi][ni][half * 2 + 0];
                float vy = aHv * acc[mi][ni][half * 2 + 1];
                if (z0) {
                    float2 xw = *(const float2*)&g_XW[rb + c];
                    float2 bb = *(const float2*)&bconv[c];
                    vx += aLv * (d2 * xw.x + bb.x);
                    vy += aLv * (d2 * xw.y + bb.y);
                }
                red2(&out[rb + c], vx, vy);
            }
        }
    }
}

// ---------------------------------------------------------------------------
extern "C" void kernel_launch(void* const* d_in, const int* in_sizes, int n_in,
                              void* d_out, int out_size) {
    const float* x  = (const float*)d_in[0];
    const int*   ei = (const int*)d_in[1];
    const float* Ls = (const float*)d_in[2];
    const float* Wh = (const float*)d_in[3];
    const float* Wc = (const float*)d_in[4];
    const float* bc = (const float*)d_in[5];
    const float* aL = (const float*)d_in[6];
    const float* aH = (const float*)d_in[7];
    float* out = (float*)d_out;

    cudaFuncSetAttribute(k_xw,   cudaFuncAttributeMaxDynamicSharedMemorySize, SM_XW);
    cudaFuncSetAttribute(k_gemm, cudaFuncAttributeMaxDynamicSharedMemorySize, SM_GEMM);

    // order chosen so ncu (-s 5 -c 1) captures k_gemm
    k_init<<<(NN * DD) / 256, 256>>>(out);
    k_deg<<<(EE + 255) / 256, 256>>>(ei);
    k_xw<<<96, 256, SM_XW>>>(x, Wh, Wc);
    k_gemm<<<dim3(96, KSPLIT), 256, SM_GEMM>>>(Ls, bc, aL, aH, out);
    k_scatter<<<(EE * 16) / 256, 256>>>(ei, aL, out);
}